// round 3
// baseline (speedup 1.0000x reference)
#include <cuda_runtime.h>
#include <math.h>

#define BB 8
#define DD 1024
#define LOWD 512
#define SPAST 8191
#define STOT 8192
#define CPB 64            // chunks (blocks) per batch
#define CHUNK 128         // rows per block
#define NWARP 8
#define NSPLIT (CPB*NWARP)   // 512 partials per batch from main kernel
#define PSTRIDE 520          // NSPLIT + 1 (current token) rounded up
#define SCALE 0.02209708691207961f  // 1/sqrt(2*1024)

// ------------------- device scratch (no allocations allowed) -------------------
__device__ float g_cur_ckv[BB*LOWD];
__device__ float g_cur_kr [BB*DD];
__device__ float g_cur_up [BB*2*DD];
__device__ float g_Cq  [BB*DD];
__device__ float g_Qc  [BB*DD];
__device__ float g_Qr  [BB*DD];
__device__ float g_Pm  [BB*PSTRIDE];
__device__ float g_Pl  [BB*PSTRIDE];
__device__ float g_Pacc[(size_t)BB*PSTRIDE*DD];   // ~17 MB
__device__ float g_attn[BB*DD];

// ------------------- zero scratch + final-out region -------------------
__global__ void zero_scratch(float* __restrict__ dout) {
    int i = blockIdx.x * 256 + threadIdx.x;           // grid covers 8*2048
    if (i < BB*LOWD)  g_cur_ckv[i] = 0.f;
    if (i < BB*DD) { g_cur_kr[i] = 0.f; g_Cq[i] = 0.f; g_Qc[i] = 0.f; g_Qr[i] = 0.f; }
    if (i < BB*2*DD)  g_cur_up[i] = 0.f;
    if (i < BB*DD)    dout[i < BB*DD ? 0 : 0] = dout[0]; // no-op guard (kept simple below)
    if (i < BB*DD)    ;                                  // (out region zero below)
    if (i < BB*DD)    ;
    if (i < BB*DD)    ;
    if (i < BB*DD && i < 8192) dout[i] = 0.f;
}

// ------------------- batched GEMV: Y[b][o] += sum_d X[b][d] * W[d][o] -------------------
// grid = (O/256, 16). Each block handles a d-chunk of Din/16, atomically accumulates.
__global__ void gemv8(const float* __restrict__ X, const float* __restrict__ W,
                      float* __restrict__ Y, int Din, int O) {
    __shared__ float sx[BB * 128];                   // up to 8 * dchunk (dchunk <= 128)
    int o = blockIdx.x * 256 + threadIdx.x;
    int dchunk = Din >> 4;                           // Din/16
    int d0 = blockIdx.y * dchunk;
    for (int i = threadIdx.x; i < BB * dchunk; i += 256) {
        int b = i / dchunk, dd = i - b * dchunk;
        sx[b * dchunk + dd] = X[b * Din + d0 + dd];
    }
    __syncthreads();
    float acc[BB];
#pragma unroll
    for (int b = 0; b < BB; b++) acc[b] = 0.f;
#pragma unroll 4
    for (int dd = 0; dd < dchunk; dd++) {
        float w = W[(size_t)(d0 + dd) * O + o];
#pragma unroll
        for (int b = 0; b < BB; b++) acc[b] = fmaf(sx[b * dchunk + dd], w, acc[b]);
    }
#pragma unroll
    for (int b = 0; b < BB; b++) atomicAdd(&Y[b * O + o], acc[b]);
}

// ------------------- main fused kernel: cache copy + scores + online softmax partials ----
__global__ void __launch_bounds__(256, 1)
fused_main(const float* __restrict__ ckv_cache, const float* __restrict__ kr_cache,
           const float* __restrict__ up_cache,
           float* __restrict__ out_ckv, float* __restrict__ out_kr, float* __restrict__ out_up) {
    int b    = blockIdx.x / CPB;
    int c    = blockIdx.x % CPB;
    int warp = threadIdx.x >> 5;
    int lane = threadIdx.x & 31;
    int s0   = c * CHUNK;
    int rows = SPAST - s0; if (rows > CHUNK) rows = CHUNK;

    // --- ckv copy (pure stream, block-wide) ---
    {
        const float4* src = (const float4*)(ckv_cache + (size_t)b * SPAST * LOWD);
        float4*       dst = (float4*)(out_ckv + (size_t)b * STOT * LOWD);
        int base  = s0 * (LOWD / 4);
        int total = rows * (LOWD / 4);
        for (int i = threadIdx.x; i < total; i += 256) dst[base + i] = src[base + i];
    }

    // --- q fragments in registers ---
    const float4* qc4 = (const float4*)(g_Qc + b * DD);
    const float4* qr4 = (const float4*)(g_Qr + b * DD);
    float4 fqc[8], fqr[8];
#pragma unroll
    for (int j = 0; j < 8; j++) { fqc[j] = qc4[lane + 32 * j]; fqr[j] = qr4[lane + 32 * j]; }

    float4 acc[8];
#pragma unroll
    for (int j = 0; j < 8; j++) acc[j] = make_float4(0.f, 0.f, 0.f, 0.f);
    float m = -1e30f, l = 0.f;

    for (int i = warp; i < CHUNK; i += NWARP) {
        int s = s0 + i;
        if (s >= SPAST) break;
        const float4* u4 = (const float4*)(up_cache + ((size_t)b * SPAST + s) * 2 * DD);
        const float4* k4 = (const float4*)(kr_cache + ((size_t)b * SPAST + s) * DD);
        float4* ou4 = (float4*)(out_up + ((size_t)b * STOT + s) * 2 * DD);
        float4* ok4 = (float4*)(out_kr + ((size_t)b * STOT + s) * DD);

        float part = 0.f;
#pragma unroll
        for (int j = 0; j < 8; j++) {                // k_up half of up row
            float4 ku = u4[lane + 32 * j];
            ou4[lane + 32 * j] = ku;
            part += ku.x * fqc[j].x + ku.y * fqc[j].y + ku.z * fqc[j].z + ku.w * fqc[j].w;
        }
#pragma unroll
        for (int j = 0; j < 8; j++) {                // kr row
            float4 kr = k4[lane + 32 * j];
            ok4[lane + 32 * j] = kr;
            part += kr.x * fqr[j].x + kr.y * fqr[j].y + kr.z * fqr[j].z + kr.w * fqr[j].w;
        }
#pragma unroll
        for (int off = 16; off; off >>= 1) part += __shfl_xor_sync(0xffffffffu, part, off);
        float sc = part * SCALE;
        float p;
        if (sc > m) {
            float f = __expf(m - sc);
            l *= f;
#pragma unroll
            for (int j = 0; j < 8; j++) {
                acc[j].x *= f; acc[j].y *= f; acc[j].z *= f; acc[j].w *= f;
            }
            m = sc; p = 1.f;
        } else {
            p = __expf(sc - m);
        }
        l += p;
#pragma unroll
        for (int j = 0; j < 8; j++) {                // v half of up row: copy + accumulate
            float4 vv = u4[256 + lane + 32 * j];
            ou4[256 + lane + 32 * j] = vv;
            acc[j].x = fmaf(p, vv.x, acc[j].x);
            acc[j].y = fmaf(p, vv.y, acc[j].y);
            acc[j].z = fmaf(p, vv.z, acc[j].z);
            acc[j].w = fmaf(p, vv.w, acc[j].w);
        }
    }

    int pidx = c * NWARP + warp;
    if (lane == 0) { g_Pm[b * PSTRIDE + pidx] = m; g_Pl[b * PSTRIDE + pidx] = l; }
    float4* pa = (float4*)(g_Pacc + ((size_t)b * PSTRIDE + pidx) * DD);
#pragma unroll
    for (int j = 0; j < 8; j++) pa[lane + 32 * j] = acc[j];
}

// ------------------- current token: copy new rows + its softmax partial -------------------
__global__ void finalize_cur(float* __restrict__ out_ckv, float* __restrict__ out_kr,
                             float* __restrict__ out_up) {
    int b = blockIdx.x, tid = threadIdx.x;
    // copy new rows into position s = SPAST
    {
        const float4* cc = (const float4*)(g_cur_ckv + b * LOWD);
        float4* oc = (float4*)(out_ckv + ((size_t)b * STOT + SPAST) * LOWD);
        for (int i = tid; i < LOWD / 4; i += 256) oc[i] = cc[i];
        const float4* ck = (const float4*)(g_cur_kr + b * DD);
        float4* ok = (float4*)(out_kr + ((size_t)b * STOT + SPAST) * DD);
        for (int i = tid; i < DD / 4; i += 256) ok[i] = ck[i];
        const float4* cu = (const float4*)(g_cur_up + b * 2 * DD);
        float4* ou = (float4*)(out_up + ((size_t)b * STOT + SPAST) * 2 * DD);
        for (int i = tid; i < 2 * DD / 4; i += 256) ou[i] = cu[i];
    }
    // score for the current token
    float part = 0.f;
    for (int i = tid; i < DD; i += 256) part += g_Qc[b * DD + i] * g_cur_up[b * 2 * DD + i];
    for (int i = tid; i < DD; i += 256) part += g_Qr[b * DD + i] * g_cur_kr[b * DD + i];
    __shared__ float red[256];
    red[tid] = part; __syncthreads();
    for (int s = 128; s; s >>= 1) { if (tid < s) red[tid] += red[tid + s]; __syncthreads(); }
    float sc = red[0] * SCALE;
    if (tid == 0) { g_Pm[b * PSTRIDE + NSPLIT] = sc; g_Pl[b * PSTRIDE + NSPLIT] = 1.f; }
    float* pa = g_Pacc + ((size_t)b * PSTRIDE + NSPLIT) * DD;
    for (int i = tid; i < DD; i += 256) pa[i] = g_cur_up[b * 2 * DD + DD + i];
}

// ------------------- combine split-KV partials -> attn -------------------
__global__ void reduce_attn() {
    int b = blockIdx.x, tid = threadIdx.x;
    __shared__ float sred[256];
    __shared__ float sw[NSPLIT + 1];
    __shared__ float sM, sL;
    float M = -1e30f;
    for (int i = tid; i <= NSPLIT; i += 256) M = fmaxf(M, g_Pm[b * PSTRIDE + i]);
    sred[tid] = M; __syncthreads();
    for (int s = 128; s; s >>= 1) { if (tid < s) sred[tid] = fmaxf(sred[tid], sred[tid + s]); __syncthreads(); }
    if (tid == 0) sM = sred[0];
    __syncthreads();
    M = sM;
    float L = 0.f;
    for (int i = tid; i <= NSPLIT; i += 256) {
        float w = __expf(g_Pm[b * PSTRIDE + i] - M);
        sw[i] = w;
        L += w * g_Pl[b * PSTRIDE + i];
    }
    sred[tid] = L; __syncthreads();
    for (int s = 128; s; s >>= 1) { if (tid < s) sred[tid] += sred[tid + s]; __syncthreads(); }
    if (tid == 0) sL = sred[0];
    __syncthreads();
    float inv = 1.f / sL;
    for (int d = tid; d < DD; d += 256) {
        float a = 0.f;
        const float* pa = g_Pacc + (size_t)b * PSTRIDE * DD + d;
#pragma unroll 4
        for (int i = 0; i <= NSPLIT; i++) a = fmaf(sw[i], pa[(size_t)i * DD], a);
        g_attn[b * DD + d] = a * inv;
    }
}

// ------------------- launch -------------------
extern "C" void kernel_launch(void* const* d_in, const int* in_sizes, int n_in,
                              void* d_out, int out_size) {
    (void)in_sizes; (void)n_in; (void)out_size;
    const float* x        = (const float*)d_in[0];
    const float* ckv_c    = (const float*)d_in[1];
    const float* kr_c     = (const float*)d_in[2];
    const float* up_c     = (const float*)d_in[3];
    const float* Wdq      = (const float*)d_in[4];
    const float* Wuq      = (const float*)d_in[5];
    const float* Wqr      = (const float*)d_in[6];
    const float* Wdkv     = (const float*)d_in[7];
    const float* Wkr      = (const float*)d_in[8];
    const float* fup      = (const float*)d_in[9];
    const float* Wo       = (const float*)d_in[10];

    float* dout    = (float*)d_out;
    float* out_att = dout;                                     // [8,1,1024]
    float* out_ckv = dout + (size_t)BB * DD;                   // [8,8192,512]
    float* out_kr  = out_ckv + (size_t)BB * STOT * LOWD;       // [8,8192,1024]
    float* out_up  = out_kr  + (size_t)BB * STOT * DD;         // [8,8192,2048]

    float *p_cur_ckv, *p_cur_kr, *p_cur_up, *p_Cq, *p_Qc, *p_Qr, *p_attn;
    cudaGetSymbolAddress((void**)&p_cur_ckv, g_cur_ckv);
    cudaGetSymbolAddress((void**)&p_cur_kr,  g_cur_kr);
    cudaGetSymbolAddress((void**)&p_cur_up,  g_cur_up);
    cudaGetSymbolAddress((void**)&p_Cq,      g_Cq);
    cudaGetSymbolAddress((void**)&p_Qc,      g_Qc);
    cudaGetSymbolAddress((void**)&p_Qr,      g_Qr);
    cudaGetSymbolAddress((void**)&p_attn,    g_attn);

    zero_scratch<<<64, 256>>>(dout);

    // projection chain (batched GEMVs, d-split 16)
    gemv8<<<dim3(LOWD / 256, 16), 256>>>(x,        Wdkv, p_cur_ckv, DD,   LOWD);
    gemv8<<<dim3(DD / 256,   16), 256>>>(x,        Wkr,  p_cur_kr,  DD,   DD);
    gemv8<<<dim3(DD / 256,   16), 256>>>(x,        Wdq,  p_Cq,      DD,   DD);
    gemv8<<<dim3(DD / 256,   16), 256>>>(p_Cq,     Wuq,  p_Qc,      DD,   DD);
    gemv8<<<dim3(DD / 256,   16), 256>>>(p_Cq,     Wqr,  p_Qr,      DD,   DD);
    gemv8<<<dim3(2 * DD / 256, 16), 256>>>(p_cur_ckv, fup, p_cur_up, LOWD, 2 * DD);

    // big fused streaming pass: copies + scores + online-softmax partials
    fused_main<<<BB * CPB, 256>>>(ckv_c, kr_c, up_c, out_ckv, out_kr, out_up);

    // current-token rows + its partial
    finalize_cur<<<BB, 256>>>(out_ckv, out_kr, out_up);

    // combine partials -> attn
    reduce_attn<<<BB, 256>>>();

    // out = attn @ Wo
    gemv8<<<dim3(DD / 256, 16), 256>>>(p_attn, Wo, out_att, DD, DD);
}

// round 4
// speedup vs baseline: 1.1586x; 1.1586x over previous
#include <cuda_runtime.h>
#include <math.h>

#define BB 8
#define DD 1024
#define LOWD 512
#define SPAST 8191
#define STOT 8192
#define CPB 128           // chunks (blocks) per batch
#define CHUNK 64          // rows per block
#define NWARP 8
#define NSPLIT (CPB*NWARP)   // 1024 partials per batch from main kernel
#define PSTRIDE 1025         // NSPLIT + 1 (current token)
#define SCALE 0.02209708691207961f  // 1/sqrt(2*1024)

// ------------------- device scratch (no allocations allowed) -------------------
__device__ float g_cur_ckv[BB*LOWD];
__device__ float g_cur_kr [BB*DD];
__device__ float g_cur_up [BB*2*DD];
__device__ float g_Cq  [BB*DD];
__device__ float g_Qc  [BB*DD];
__device__ float g_Qr  [BB*DD];
__device__ float g_Pm  [BB*PSTRIDE];
__device__ float g_Pl  [BB*PSTRIDE];
__device__ float g_Pacc[(size_t)BB*PSTRIDE*DD];   // ~33.6 MB
__device__ float g_attn[BB*DD];

// ------------------- zero scratch + final-out region -------------------
__global__ void zero_scratch(float* __restrict__ dout) {
    int i = blockIdx.x * 256 + threadIdx.x;           // grid: 64*256 = 16384
    if (i < BB*LOWD)  g_cur_ckv[i] = 0.f;
    if (i < BB*DD) { g_cur_kr[i] = 0.f; g_Cq[i] = 0.f; g_Qc[i] = 0.f; g_Qr[i] = 0.f; }
    if (i < BB*2*DD)  g_cur_up[i] = 0.f;
    if (i < BB*DD)    dout[i] = 0.f;
}

// ------------------- stage 1: [cur_ckv | cur_kr | Cq] = x @ [Wdkv | Wkr | Wdq] --------
// grid (10, 8): 2560 outputs tiled by 256; Din=1024 split by 8 (128 each); atomic accum.
__global__ void proj1(const float* __restrict__ x,
                      const float* __restrict__ Wdkv, const float* __restrict__ Wkr,
                      const float* __restrict__ Wdq) {
    __shared__ float sx[BB * 128];
    int og = blockIdx.x * 256 + threadIdx.x;         // 0..2559
    int d0 = blockIdx.y * 128;
    for (int i = threadIdx.x; i < BB * 128; i += 256) {
        int b = i >> 7, dd = i & 127;
        sx[i] = x[b * DD + d0 + dd];
    }
    __syncthreads();
    const float* W; float* Y; int O; int col;
    if (og < 512)       { W = Wdkv; Y = g_cur_ckv; O = LOWD; col = og; }
    else if (og < 1536) { W = Wkr;  Y = g_cur_kr;  O = DD;   col = og - 512; }
    else                { W = Wdq;  Y = g_Cq;      O = DD;   col = og - 1536; }
    float acc[BB];
#pragma unroll
    for (int b = 0; b < BB; b++) acc[b] = 0.f;
#pragma unroll 8
    for (int dd = 0; dd < 128; dd++) {
        float w = W[(size_t)(d0 + dd) * O + col];
#pragma unroll
        for (int b = 0; b < BB; b++) acc[b] = fmaf(sx[(b << 7) + dd], w, acc[b]);
    }
#pragma unroll
    for (int b = 0; b < BB; b++) atomicAdd(&Y[b * O + col], acc[b]);
}

// ------------------- stage 2: [Qc | Qr] = Cq @ [Wuq|Wqr]; cur_up = cur_ckv @ fup -------
// grid (16, 8): 4096 outputs tiled by 256. Ranges align to block boundaries.
__global__ void proj2(const float* __restrict__ Wuq, const float* __restrict__ Wqr,
                      const float* __restrict__ fup) {
    __shared__ float sx[BB * 128];
    int og = blockIdx.x * 256 + threadIdx.x;         // 0..4095
    const float* W; const float* X; float* Y; int O, col, Din, dchunk;
    if (og < 1024)      { W = Wuq; X = g_Cq;      Y = g_Qc;     O = DD;     col = og;        Din = DD;   }
    else if (og < 2048) { W = Wqr; X = g_Cq;      Y = g_Qr;     O = DD;     col = og - 1024; Din = DD;   }
    else                { W = fup; X = g_cur_ckv; Y = g_cur_up; O = 2 * DD; col = og - 2048; Din = LOWD; }
    dchunk = Din >> 3;
    int d0 = blockIdx.y * dchunk;
    for (int i = threadIdx.x; i < BB * dchunk; i += 256) {
        int b = i / dchunk, dd = i - b * dchunk;
        sx[b * dchunk + dd] = X[b * Din + d0 + dd];
    }
    __syncthreads();
    float acc[BB];
#pragma unroll
    for (int b = 0; b < BB; b++) acc[b] = 0.f;
#pragma unroll 8
    for (int dd = 0; dd < dchunk; dd++) {
        float w = W[(size_t)(d0 + dd) * O + col];
#pragma unroll
        for (int b = 0; b < BB; b++) acc[b] = fmaf(sx[b * dchunk + dd], w, acc[b]);
    }
#pragma unroll
    for (int b = 0; b < BB; b++) atomicAdd(&Y[b * O + col], acc[b]);
}

// ------------------- main fused kernel: cache copy + scores + online softmax partials ----
__global__ void __launch_bounds__(256)
fused_main(const float* __restrict__ ckv_cache, const float* __restrict__ kr_cache,
           const float* __restrict__ up_cache,
           float* __restrict__ out_ckv, float* __restrict__ out_kr, float* __restrict__ out_up) {
    __shared__ float4 sqc[DD / 4];                   // 4 KB
    __shared__ float4 sqr[DD / 4];                   // 4 KB
    int b    = blockIdx.x / CPB;
    int c    = blockIdx.x % CPB;
    int warp = threadIdx.x >> 5;
    int lane = threadIdx.x & 31;
    int s0   = c * CHUNK;
    int rows = SPAST - s0; if (rows > CHUNK) rows = CHUNK;

    // --- q into shared ---
    {
        const float4* qc4 = (const float4*)(g_Qc + b * DD);
        const float4* qr4 = (const float4*)(g_Qr + b * DD);
        if (threadIdx.x < 256) {
            sqc[threadIdx.x] = qc4[threadIdx.x];
            sqr[threadIdx.x] = qr4[threadIdx.x];
        }
    }

    // --- ckv copy (pure stream, block-wide) ---
    {
        const float4* src = (const float4*)(ckv_cache + (size_t)b * SPAST * LOWD);
        float4*       dst = (float4*)(out_ckv + (size_t)b * STOT * LOWD);
        int base  = s0 * (LOWD / 4);
        int total = rows * (LOWD / 4);
        for (int i = threadIdx.x; i < total; i += 256)
            __stcs(dst + base + i, __ldcs(src + base + i));
    }
    __syncthreads();

    float4 acc[8];
#pragma unroll
    for (int j = 0; j < 8; j++) acc[j] = make_float4(0.f, 0.f, 0.f, 0.f);
    float m = -1e30f, l = 0.f;

    for (int i = warp; i < CHUNK; i += NWARP) {
        int s = s0 + i;
        if (s >= SPAST) break;
        const float4* u4 = (const float4*)(up_cache + ((size_t)b * SPAST + s) * 2 * DD);
        const float4* k4 = (const float4*)(kr_cache + ((size_t)b * SPAST + s) * DD);
        float4* ou4 = (float4*)(out_up + ((size_t)b * STOT + s) * 2 * DD);
        float4* ok4 = (float4*)(out_kr + ((size_t)b * STOT + s) * DD);

        float part = 0.f;
#pragma unroll
        for (int j = 0; j < 8; j++) {                // k_up half of up row
            float4 ku = __ldcs(u4 + lane + 32 * j);
            __stcs(ou4 + lane + 32 * j, ku);
            float4 q = sqc[lane + 32 * j];
            part += ku.x * q.x + ku.y * q.y + ku.z * q.z + ku.w * q.w;
        }
#pragma unroll
        for (int j = 0; j < 8; j++) {                // kr row
            float4 kr = __ldcs(k4 + lane + 32 * j);
            __stcs(ok4 + lane + 32 * j, kr);
            float4 q = sqr[lane + 32 * j];
            part += kr.x * q.x + kr.y * q.y + kr.z * q.z + kr.w * q.w;
        }
#pragma unroll
        for (int off = 16; off; off >>= 1) part += __shfl_xor_sync(0xffffffffu, part, off);
        float sc = part * SCALE;
        float p;
        if (sc > m) {
            float f = __expf(m - sc);
            l *= f;
#pragma unroll
            for (int j = 0; j < 8; j++) {
                acc[j].x *= f; acc[j].y *= f; acc[j].z *= f; acc[j].w *= f;
            }
            m = sc; p = 1.f;
        } else {
            p = __expf(sc - m);
        }
        l += p;
#pragma unroll
        for (int j = 0; j < 8; j++) {                // v half of up row: copy + accumulate
            float4 vv = __ldcs(u4 + 256 + lane + 32 * j);
            __stcs(ou4 + 256 + lane + 32 * j, vv);
            acc[j].x = fmaf(p, vv.x, acc[j].x);
            acc[j].y = fmaf(p, vv.y, acc[j].y);
            acc[j].z = fmaf(p, vv.z, acc[j].z);
            acc[j].w = fmaf(p, vv.w, acc[j].w);
        }
    }

    int pidx = c * NWARP + warp;
    if (lane == 0) { g_Pm[b * PSTRIDE + pidx] = m; g_Pl[b * PSTRIDE + pidx] = l; }
    float4* pa = (float4*)(g_Pacc + ((size_t)b * PSTRIDE + pidx) * DD);
#pragma unroll
    for (int j = 0; j < 8; j++) __stcs(pa + lane + 32 * j, acc[j]);
}

// ------------------- current token: copy new rows + its softmax partial -------------------
__global__ void finalize_cur(float* __restrict__ out_ckv, float* __restrict__ out_kr,
                             float* __restrict__ out_up) {
    int b = blockIdx.x, tid = threadIdx.x;
    // copy new rows into position s = SPAST
    {
        const float4* cc = (const float4*)(g_cur_ckv + b * LOWD);
        float4* oc = (float4*)(out_ckv + ((size_t)b * STOT + SPAST) * LOWD);
        for (int i = tid; i < LOWD / 4; i += 256) oc[i] = cc[i];
        const float4* ck = (const float4*)(g_cur_kr + b * DD);
        float4* ok = (float4*)(out_kr + ((size_t)b * STOT + SPAST) * DD);
        for (int i = tid; i < DD / 4; i += 256) ok[i] = ck[i];
        const float4* cu = (const float4*)(g_cur_up + b * 2 * DD);
        float4* ou = (float4*)(out_up + ((size_t)b * STOT + SPAST) * 2 * DD);
        for (int i = tid; i < 2 * DD / 4; i += 256) ou[i] = cu[i];
    }
    // score for the current token
    float part = 0.f;
    for (int i = tid; i < DD; i += 256) part += g_Qc[b * DD + i] * g_cur_up[b * 2 * DD + i];
    for (int i = tid; i < DD; i += 256) part += g_Qr[b * DD + i] * g_cur_kr[b * DD + i];
    __shared__ float red[256];
    red[tid] = part; __syncthreads();
    for (int s = 128; s; s >>= 1) { if (tid < s) red[tid] += red[tid + s]; __syncthreads(); }
    float sc = red[0] * SCALE;
    if (tid == 0) { g_Pm[b * PSTRIDE + NSPLIT] = sc; g_Pl[b * PSTRIDE + NSPLIT] = 1.f; }
    float* pa = g_Pacc + ((size_t)b * PSTRIDE + NSPLIT) * DD;
    for (int i = tid; i < DD; i += 256) pa[i] = g_cur_up[b * 2 * DD + DD + i];
}

// ------------------- combine split-KV partials -> attn -------------------
// grid (BB, 4): each block owns batch b and a 256-wide d slice.
__global__ void reduce_attn() {
    int b = blockIdx.x, tid = threadIdx.x;
    int d = blockIdx.y * 256 + tid;
    __shared__ float sred[256];
    __shared__ float sw[PSTRIDE];
    __shared__ float sM, sL;
    float M = -1e30f;
    for (int i = tid; i < PSTRIDE; i += 256) M = fmaxf(M, g_Pm[b * PSTRIDE + i]);
    sred[tid] = M; __syncthreads();
    for (int s = 128; s; s >>= 1) { if (tid < s) sred[tid] = fmaxf(sred[tid], sred[tid + s]); __syncthreads(); }
    if (tid == 0) sM = sred[0];
    __syncthreads();
    M = sM;
    float L = 0.f;
    for (int i = tid; i < PSTRIDE; i += 256) {
        float w = __expf(g_Pm[b * PSTRIDE + i] - M);
        sw[i] = w;
        L += w * g_Pl[b * PSTRIDE + i];
    }
    sred[tid] = L; __syncthreads();
    for (int s = 128; s; s >>= 1) { if (tid < s) sred[tid] += sred[tid + s]; __syncthreads(); }
    if (tid == 0) sL = sred[0];
    __syncthreads();
    float inv = 1.f / sL;
    float a = 0.f;
    const float* pa = g_Pacc + (size_t)b * PSTRIDE * DD + d;
#pragma unroll 8
    for (int i = 0; i < PSTRIDE; i++) a = fmaf(sw[i], __ldcs(pa + (size_t)i * DD), a);
    g_attn[b * DD + d] = a * inv;
}

// ------------------- out = attn @ Wo -------------------
// grid (4, 8): 1024 outputs tiled by 256; Din split 8.
__global__ void gemv_wo(const float* __restrict__ Wo, float* __restrict__ Y) {
    __shared__ float sx[BB * 128];
    int o = blockIdx.x * 256 + threadIdx.x;
    int d0 = blockIdx.y * 128;
    for (int i = threadIdx.x; i < BB * 128; i += 256) {
        int b = i >> 7, dd = i & 127;
        sx[i] = g_attn[b * DD + d0 + dd];
    }
    __syncthreads();
    float acc[BB];
#pragma unroll
    for (int b = 0; b < BB; b++) acc[b] = 0.f;
#pragma unroll 8
    for (int dd = 0; dd < 128; dd++) {
        float w = Wo[(size_t)(d0 + dd) * DD + o];
#pragma unroll
        for (int b = 0; b < BB; b++) acc[b] = fmaf(sx[(b << 7) + dd], w, acc[b]);
    }
#pragma unroll
    for (int b = 0; b < BB; b++) atomicAdd(&Y[b * DD + o], acc[b]);
}

// ------------------- launch -------------------
extern "C" void kernel_launch(void* const* d_in, const int* in_sizes, int n_in,
                              void* d_out, int out_size) {
    (void)in_sizes; (void)n_in; (void)out_size;
    const float* x        = (const float*)d_in[0];
    const float* ckv_c    = (const float*)d_in[1];
    const float* kr_c     = (const float*)d_in[2];
    const float* up_c     = (const float*)d_in[3];
    const float* Wdq      = (const float*)d_in[4];
    const float* Wuq      = (const float*)d_in[5];
    const float* Wqr      = (const float*)d_in[6];
    const float* Wdkv     = (const float*)d_in[7];
    const float* Wkr      = (const float*)d_in[8];
    const float* fup      = (const float*)d_in[9];
    const float* Wo       = (const float*)d_in[10];

    float* dout    = (float*)d_out;
    float* out_att = dout;                                     // [8,1,1024]
    float* out_ckv = dout + (size_t)BB * DD;                   // [8,8192,512]
    float* out_kr  = out_ckv + (size_t)BB * STOT * LOWD;       // [8,8192,1024]
    float* out_up  = out_kr  + (size_t)BB * STOT * DD;         // [8,8192,2048]

    zero_scratch<<<64, 256>>>(dout);

    // projection chain (3 fused launches)
    proj1<<<dim3(10, 8), 256>>>(x, Wdkv, Wkr, Wdq);
    proj2<<<dim3(16, 8), 256>>>(Wuq, Wqr, fup);

    // big fused streaming pass: copies + scores + online-softmax partials
    fused_main<<<BB * CPB, 256>>>(ckv_c, kr_c, up_c, out_ckv, out_kr, out_up);

    // current-token rows + its partial
    finalize_cur<<<BB, 256>>>(out_ckv, out_kr, out_up);

    // combine partials -> attn
    reduce_attn<<<dim3(BB, 4), 256>>>();

    // out = attn @ Wo
    gemv_wo<<<dim3(4, 8), 256>>>(Wo, out_att);
}

// round 5
// speedup vs baseline: 1.4659x; 1.2652x over previous
#include <cuda_runtime.h>
#include <math.h>

#define BB 8
#define DD 1024
#define LOWD 512
#define SPAST 8191
#define STOT 8192
#define CPB 128           // chunks (blocks) per batch
#define CHUNK 64          // rows per block
#define NWARP 8
#define SCALE 0.02209708691207961f  // 1/sqrt(2*1024)
#define VCHUNK 128        // rows per wv_k block

// ------------------- device scratch (no allocations allowed) -------------------
__device__ float g_cur_ckv[BB*LOWD];
__device__ float g_cur_kr [BB*DD];
__device__ float g_cur_up [BB*2*DD];
__device__ float g_Cq  [BB*DD];
__device__ float g_Qc  [BB*DD];
__device__ float g_Qr  [BB*DD];
__device__ float g_score[BB*STOT];
__device__ float g_w    [BB*STOT];
__device__ float g_attn [BB*DD];

// ------------------- zero scratch + out_att region -------------------
__global__ void zero_scratch(float* __restrict__ dout) {
    int i = blockIdx.x * 256 + threadIdx.x;           // grid: 64*256 = 16384
    if (i < BB*LOWD)  g_cur_ckv[i] = 0.f;
    if (i < BB*DD) { g_cur_kr[i] = 0.f; g_Cq[i] = 0.f; g_Qc[i] = 0.f;
                     g_Qr[i] = 0.f; g_attn[i] = 0.f; }
    if (i < BB*2*DD)  g_cur_up[i] = 0.f;
    if (i < BB*DD)    dout[i] = 0.f;
}

// ------------------- stage 1: [cur_ckv | cur_kr | Cq] = x @ [Wdkv | Wkr | Wdq] --------
// grid (10, 32): 2560 outputs tiled by 256; Din=1024 split 32 (32 each); atomic accum.
__global__ void proj1(const float* __restrict__ x,
                      const float* __restrict__ Wdkv, const float* __restrict__ Wkr,
                      const float* __restrict__ Wdq) {
    __shared__ float sx[BB * 32];
    int og = blockIdx.x * 256 + threadIdx.x;         // 0..2559
    int d0 = blockIdx.y * 32;
    if (threadIdx.x < BB * 32) {
        int b = threadIdx.x >> 5, dd = threadIdx.x & 31;
        sx[threadIdx.x] = x[b * DD + d0 + dd];
    }
    __syncthreads();
    const float* W; float* Y; int O; int col;
    if (og < 512)       { W = Wdkv; Y = g_cur_ckv; O = LOWD; col = og; }
    else if (og < 1536) { W = Wkr;  Y = g_cur_kr;  O = DD;   col = og - 512; }
    else                { W = Wdq;  Y = g_Cq;      O = DD;   col = og - 1536; }
    float acc[BB];
#pragma unroll
    for (int b = 0; b < BB; b++) acc[b] = 0.f;
#pragma unroll
    for (int dd = 0; dd < 32; dd++) {
        float w = W[(size_t)(d0 + dd) * O + col];
#pragma unroll
        for (int b = 0; b < BB; b++) acc[b] = fmaf(sx[(b << 5) + dd], w, acc[b]);
    }
#pragma unroll
    for (int b = 0; b < BB; b++) atomicAdd(&Y[b * O + col], acc[b]);
}

// ------------------- stage 2: [Qc | Qr] = Cq @ [Wuq|Wqr]; cur_up = cur_ckv @ fup -------
// grid (16, 32): 4096 outputs tiled by 256. Ranges align to block boundaries.
__global__ void proj2(const float* __restrict__ Wuq, const float* __restrict__ Wqr,
                      const float* __restrict__ fup) {
    __shared__ float sx[BB * 32];
    int og = blockIdx.x * 256 + threadIdx.x;         // 0..4095
    const float* W; const float* X; float* Y; int O, col, Din;
    if (og < 1024)      { W = Wuq; X = g_Cq;      Y = g_Qc;     O = DD;     col = og;        Din = DD;   }
    else if (og < 2048) { W = Wqr; X = g_Cq;      Y = g_Qr;     O = DD;     col = og - 1024; Din = DD;   }
    else                { W = fup; X = g_cur_ckv; Y = g_cur_up; O = 2 * DD; col = og - 2048; Din = LOWD; }
    int dchunk = Din >> 5;                            // 32 or 16
    int d0 = blockIdx.y * dchunk;
    if (threadIdx.x < BB * dchunk) {
        int b = threadIdx.x / dchunk, dd = threadIdx.x - b * dchunk;
        sx[b * dchunk + dd] = X[b * Din + d0 + dd];
    }
    __syncthreads();
    float acc[BB];
#pragma unroll
    for (int b = 0; b < BB; b++) acc[b] = 0.f;
#pragma unroll 16
    for (int dd = 0; dd < dchunk; dd++) {
        float w = W[(size_t)(d0 + dd) * O + col];
#pragma unroll
        for (int b = 0; b < BB; b++) acc[b] = fmaf(sx[b * dchunk + dd], w, acc[b]);
    }
#pragma unroll
    for (int b = 0; b < BB; b++) atomicAdd(&Y[b * O + col], acc[b]);
}

// ------------------- main streaming kernel: cache copy + raw scores ----------------------
// No accumulator, no softmax chain -> low regs, high occupancy, max MLP.
__global__ void __launch_bounds__(256)
stream_score(const float* __restrict__ ckv_cache, const float* __restrict__ kr_cache,
             const float* __restrict__ up_cache,
             float* __restrict__ out_ckv, float* __restrict__ out_kr, float* __restrict__ out_up) {
    __shared__ float4 sqc[DD / 4];                   // 4 KB
    __shared__ float4 sqr[DD / 4];                   // 4 KB
    int b    = blockIdx.x / CPB;
    int c    = blockIdx.x % CPB;
    int warp = threadIdx.x >> 5;
    int lane = threadIdx.x & 31;
    int s0   = c * CHUNK;
    int rows = SPAST - s0; if (rows > CHUNK) rows = CHUNK;

    // --- q into shared ---
    sqc[threadIdx.x] = ((const float4*)(g_Qc + b * DD))[threadIdx.x];
    sqr[threadIdx.x] = ((const float4*)(g_Qr + b * DD))[threadIdx.x];

    // --- ckv copy (pure stream, block-wide) ---
    {
        const float4* src = (const float4*)(ckv_cache + (size_t)b * SPAST * LOWD);
        float4*       dst = (float4*)(out_ckv + (size_t)b * STOT * LOWD);
        int base  = s0 * (LOWD / 4);
        int total = rows * (LOWD / 4);
        for (int i = threadIdx.x; i < total; i += 256)
            __stcs(dst + base + i, __ldcs(src + base + i));
    }
    __syncthreads();

    for (int i = warp; i < CHUNK; i += NWARP) {
        int s = s0 + i;
        if (s >= SPAST) break;
        const float4* u4 = (const float4*)(up_cache + ((size_t)b * SPAST + s) * 2 * DD);
        const float4* k4 = (const float4*)(kr_cache + ((size_t)b * SPAST + s) * DD);
        float4* ou4 = (float4*)(out_up + ((size_t)b * STOT + s) * 2 * DD);
        float4* ok4 = (float4*)(out_kr + ((size_t)b * STOT + s) * DD);

        float part = 0.f;
#pragma unroll
        for (int j = 0; j < 8; j++) {                // k_up half of up row: copy + dot
            float4 ku = __ldcs(u4 + lane + 32 * j);
            __stcs(ou4 + lane + 32 * j, ku);
            float4 q = sqc[lane + 32 * j];
            part += ku.x * q.x + ku.y * q.y + ku.z * q.z + ku.w * q.w;
        }
#pragma unroll
        for (int j = 0; j < 8; j++) {                // kr row: copy + dot
            float4 kr = __ldcs(k4 + lane + 32 * j);
            __stcs(ok4 + lane + 32 * j, kr);
            float4 q = sqr[lane + 32 * j];
            part += kr.x * q.x + kr.y * q.y + kr.z * q.z + kr.w * q.w;
        }
#pragma unroll
        for (int j = 0; j < 8; j++) {                // v half of up row: pure copy
            __stcs(ou4 + 256 + lane + 32 * j, __ldcs(u4 + 256 + lane + 32 * j));
        }
#pragma unroll
        for (int off = 16; off; off >>= 1) part += __shfl_xor_sync(0xffffffffu, part, off);
        if (lane == 0) g_score[b * STOT + s] = part * SCALE;
    }
}

// ------------------- current token: copy new rows + raw score -------------------
__global__ void finalize_cur(float* __restrict__ out_ckv, float* __restrict__ out_kr,
                             float* __restrict__ out_up) {
    int b = blockIdx.x, tid = threadIdx.x;
    {
        const float4* cc = (const float4*)(g_cur_ckv + b * LOWD);
        float4* oc = (float4*)(out_ckv + ((size_t)b * STOT + SPAST) * LOWD);
        for (int i = tid; i < LOWD / 4; i += 256) oc[i] = cc[i];
        const float4* ck = (const float4*)(g_cur_kr + b * DD);
        float4* ok = (float4*)(out_kr + ((size_t)b * STOT + SPAST) * DD);
        for (int i = tid; i < DD / 4; i += 256) ok[i] = ck[i];
        const float4* cu = (const float4*)(g_cur_up + b * 2 * DD);
        float4* ou = (float4*)(out_up + ((size_t)b * STOT + SPAST) * 2 * DD);
        for (int i = tid; i < 2 * DD / 4; i += 256) ou[i] = cu[i];
    }
    float part = 0.f;
    for (int i = tid; i < DD; i += 256) part += g_Qc[b * DD + i] * g_cur_up[b * 2 * DD + i];
    for (int i = tid; i < DD; i += 256) part += g_Qr[b * DD + i] * g_cur_kr[b * DD + i];
    __shared__ float red[256];
    red[tid] = part; __syncthreads();
    for (int s = 128; s; s >>= 1) { if (tid < s) red[tid] += red[tid + s]; __syncthreads(); }
    if (tid == 0) g_score[b * STOT + SPAST] = red[0] * SCALE;
}

// ------------------- exact softmax over 8192 scores -> normalized weights ---------------
__global__ void softmax_k() {
    int b = blockIdx.x, tid = threadIdx.x;
    __shared__ float sred[256];
    __shared__ float sM, sL;
    float M = -1e30f;
    for (int i = tid; i < STOT; i += 256) M = fmaxf(M, g_score[b * STOT + i]);
    sred[tid] = M; __syncthreads();
    for (int s = 128; s; s >>= 1) { if (tid < s) sred[tid] = fmaxf(sred[tid], sred[tid + s]); __syncthreads(); }
    if (tid == 0) sM = sred[0];
    __syncthreads();
    M = sM;
    float L = 0.f;
    for (int i = tid; i < STOT; i += 256) {
        float e = __expf(g_score[b * STOT + i] - M);
        g_w[b * STOT + i] = e;
        L += e;
    }
    sred[tid] = L; __syncthreads();
    for (int s = 128; s; s >>= 1) { if (tid < s) sred[tid] += sred[tid + s]; __syncthreads(); }
    if (tid == 0) sL = sred[0];
    __syncthreads();
    float inv = 1.f / sL;
    for (int i = tid; i < STOT; i += 256) g_w[b * STOT + i] *= inv;
}

// ------------------- attn = w @ v (v = second half of out_up rows) ----------------------
// grid (BB, STOT/VCHUNK) = (8, 64). Each block: 128 rows x full 1024-d, atomic accum.
__global__ void __launch_bounds__(256)
wv_k(const float* __restrict__ out_up) {
    __shared__ float sw[VCHUNK];
    int b = blockIdx.x, tid = threadIdx.x;
    int s0 = blockIdx.y * VCHUNK;
    if (tid < VCHUNK) sw[tid] = g_w[b * STOT + s0 + tid];
    __syncthreads();
    // thread tid covers d = [4*tid, 4*tid+3]
    const float4* base = (const float4*)out_up + ((size_t)(b * STOT + s0)) * (2 * DD / 4)
                         + (DD / 4) + tid;
    float4 a0 = make_float4(0.f,0.f,0.f,0.f), a1 = a0, a2 = a0, a3 = a0;
#pragma unroll 4
    for (int r = 0; r < VCHUNK; r += 4) {
        float4 v0 = __ldcs(base + (size_t)(r + 0) * (2 * DD / 4));
        float4 v1 = __ldcs(base + (size_t)(r + 1) * (2 * DD / 4));
        float4 v2 = __ldcs(base + (size_t)(r + 2) * (2 * DD / 4));
        float4 v3 = __ldcs(base + (size_t)(r + 3) * (2 * DD / 4));
        float w0 = sw[r], w1 = sw[r+1], w2 = sw[r+2], w3 = sw[r+3];
        a0.x = fmaf(w0, v0.x, a0.x); a0.y = fmaf(w0, v0.y, a0.y);
        a0.z = fmaf(w0, v0.z, a0.z); a0.w = fmaf(w0, v0.w, a0.w);
        a1.x = fmaf(w1, v1.x, a1.x); a1.y = fmaf(w1, v1.y, a1.y);
        a1.z = fmaf(w1, v1.z, a1.z); a1.w = fmaf(w1, v1.w, a1.w);
        a2.x = fmaf(w2, v2.x, a2.x); a2.y = fmaf(w2, v2.y, a2.y);
        a2.z = fmaf(w2, v2.z, a2.z); a2.w = fmaf(w2, v2.w, a2.w);
        a3.x = fmaf(w3, v3.x, a3.x); a3.y = fmaf(w3, v3.y, a3.y);
        a3.z = fmaf(w3, v3.z, a3.z); a3.w = fmaf(w3, v3.w, a3.w);
    }
    float4 a;
    a.x = (a0.x + a1.x) + (a2.x + a3.x);
    a.y = (a0.y + a1.y) + (a2.y + a3.y);
    a.z = (a0.z + a1.z) + (a2.z + a3.z);
    a.w = (a0.w + a1.w) + (a2.w + a3.w);
    float* dst = g_attn + b * DD + 4 * tid;
    atomicAdd(dst + 0, a.x);
    atomicAdd(dst + 1, a.y);
    atomicAdd(dst + 2, a.z);
    atomicAdd(dst + 3, a.w);
}

// ------------------- out = attn @ Wo -------------------
// grid (4, 32): 1024 outputs tiled by 256; Din split 32.
__global__ void gemv_wo(const float* __restrict__ Wo, float* __restrict__ Y) {
    __shared__ float sx[BB * 32];
    int o = blockIdx.x * 256 + threadIdx.x;
    int d0 = blockIdx.y * 32;
    if (threadIdx.x < BB * 32) {
        int b = threadIdx.x >> 5, dd = threadIdx.x & 31;
        sx[threadIdx.x] = g_attn[b * DD + d0 + dd];
    }
    __syncthreads();
    float acc[BB];
#pragma unroll
    for (int b = 0; b < BB; b++) acc[b] = 0.f;
#pragma unroll
    for (int dd = 0; dd < 32; dd++) {
        float w = Wo[(size_t)(d0 + dd) * DD + o];
#pragma unroll
        for (int b = 0; b < BB; b++) acc[b] = fmaf(sx[(b << 5) + dd], w, acc[b]);
    }
#pragma unroll
    for (int b = 0; b < BB; b++) atomicAdd(&Y[b * DD + o], acc[b]);
}

// ------------------- launch -------------------
extern "C" void kernel_launch(void* const* d_in, const int* in_sizes, int n_in,
                              void* d_out, int out_size) {
    (void)in_sizes; (void)n_in; (void)out_size;
    const float* x        = (const float*)d_in[0];
    const float* ckv_c    = (const float*)d_in[1];
    const float* kr_c     = (const float*)d_in[2];
    const float* up_c     = (const float*)d_in[3];
    const float* Wdq      = (const float*)d_in[4];
    const float* Wuq      = (const float*)d_in[5];
    const float* Wqr      = (const float*)d_in[6];
    const float* Wdkv     = (const float*)d_in[7];
    const float* Wkr      = (const float*)d_in[8];
    const float* fup      = (const float*)d_in[9];
    const float* Wo       = (const float*)d_in[10];

    float* dout    = (float*)d_out;
    float* out_att = dout;                                     // [8,1,1024]
    float* out_ckv = dout + (size_t)BB * DD;                   // [8,8192,512]
    float* out_kr  = out_ckv + (size_t)BB * STOT * LOWD;       // [8,8192,1024]
    float* out_up  = out_kr  + (size_t)BB * STOT * DD;         // [8,8192,2048]

    zero_scratch<<<64, 256>>>(dout);

    // projection chain (2 fused launches, deep d-split for occupancy)
    proj1<<<dim3(10, 32), 256>>>(x, Wdkv, Wkr, Wdq);
    proj2<<<dim3(16, 32), 256>>>(Wuq, Wqr, fup);

    // big streaming pass: copies + raw scores (no softmax, no accumulators)
    stream_score<<<BB * CPB, 256>>>(ckv_c, kr_c, up_c, out_ckv, out_kr, out_up);

    // current-token rows + its raw score
    finalize_cur<<<BB, 256>>>(out_ckv, out_kr, out_up);

    // exact softmax -> normalized weights
    softmax_k<<<BB, 256>>>();

    // attn = w @ v (reads v back from out_up)
    wv_k<<<dim3(BB, STOT / VCHUNK), 256>>>(out_up);

    // out = attn @ Wo
    gemv_wo<<<dim3(4, 32), 256>>>(Wo, out_att);
}

// round 6
// speedup vs baseline: 1.7289x; 1.1794x over previous
#include <cuda_runtime.h>
#include <math.h>

#define BB 8
#define DD 1024
#define LOWD 512
#define SPAST 8191
#define STOT 8192
#define CPB 256           // chunks (blocks) per batch
#define CHUNK 32          // rows per block
#define NWARP 8
#define SCALE 0.02209708691207961f  // 1/sqrt(2*1024)
#define VCHUNK 128        // rows per wv_k block

// ------------------- device scratch (no allocations allowed) -------------------
__device__ float g_cur_ckv[BB*LOWD];
__device__ float g_cur_kr [BB*DD];
__device__ float g_cur_up [BB*2*DD];
__device__ float g_Cq  [BB*DD];
__device__ float g_Qc  [BB*DD];
__device__ float g_Qr  [BB*DD];
__device__ float g_score[BB*STOT];
__device__ float g_w    [BB*STOT];
__device__ float g_attn [BB*DD];

// ------------------- zero scratch + out_att region -------------------
__global__ void zero_scratch(float* __restrict__ dout) {
    int i = blockIdx.x * 256 + threadIdx.x;           // grid: 64*256 = 16384
    if (i < BB*LOWD)  g_cur_ckv[i] = 0.f;
    if (i < BB*DD) { g_cur_kr[i] = 0.f; g_Cq[i] = 0.f; g_Qc[i] = 0.f;
                     g_Qr[i] = 0.f; g_attn[i] = 0.f; }
    if (i < BB*2*DD)  g_cur_up[i] = 0.f;
    if (i < BB*DD)    dout[i] = 0.f;
}

// ------------------- stage 1: [cur_ckv | cur_kr | Cq] = x @ [Wdkv | Wkr | Wdq] --------
// grid (10, 32): 2560 outputs tiled by 256; Din=1024 split 32 (32 each); atomic accum.
__global__ void proj1(const float* __restrict__ x,
                      const float* __restrict__ Wdkv, const float* __restrict__ Wkr,
                      const float* __restrict__ Wdq) {
    __shared__ float sx[BB * 32];
    int og = blockIdx.x * 256 + threadIdx.x;         // 0..2559
    int d0 = blockIdx.y * 32;
    if (threadIdx.x < BB * 32) {
        int b = threadIdx.x >> 5, dd = threadIdx.x & 31;
        sx[threadIdx.x] = x[b * DD + d0 + dd];
    }
    __syncthreads();
    const float* W; float* Y; int O; int col;
    if (og < 512)       { W = Wdkv; Y = g_cur_ckv; O = LOWD; col = og; }
    else if (og < 1536) { W = Wkr;  Y = g_cur_kr;  O = DD;   col = og - 512; }
    else                { W = Wdq;  Y = g_Cq;      O = DD;   col = og - 1536; }
    float acc[BB];
#pragma unroll
    for (int b = 0; b < BB; b++) acc[b] = 0.f;
#pragma unroll
    for (int dd = 0; dd < 32; dd++) {
        float w = W[(size_t)(d0 + dd) * O + col];
#pragma unroll
        for (int b = 0; b < BB; b++) acc[b] = fmaf(sx[(b << 5) + dd], w, acc[b]);
    }
#pragma unroll
    for (int b = 0; b < BB; b++) atomicAdd(&Y[b * O + col], acc[b]);
}

// ------------------- stage 2: [Qc | Qr] = Cq @ [Wuq|Wqr]; cur_up = cur_ckv @ fup -------
// grid (16, 32): 4096 outputs tiled by 256. Ranges align to block boundaries.
__global__ void proj2(const float* __restrict__ Wuq, const float* __restrict__ Wqr,
                      const float* __restrict__ fup) {
    __shared__ float sx[BB * 32];
    int og = blockIdx.x * 256 + threadIdx.x;         // 0..4095
    const float* W; const float* X; float* Y; int O, col, Din;
    if (og < 1024)      { W = Wuq; X = g_Cq;      Y = g_Qc;     O = DD;     col = og;        Din = DD;   }
    else if (og < 2048) { W = Wqr; X = g_Cq;      Y = g_Qr;     O = DD;     col = og - 1024; Din = DD;   }
    else                { W = fup; X = g_cur_ckv; Y = g_cur_up; O = 2 * DD; col = og - 2048; Din = LOWD; }
    int dchunk = Din >> 5;                            // 32 or 16
    int d0 = blockIdx.y * dchunk;
    if (threadIdx.x < BB * dchunk) {
        int b = threadIdx.x / dchunk, dd = threadIdx.x - b * dchunk;
        sx[b * dchunk + dd] = X[b * Din + d0 + dd];
    }
    __syncthreads();
    float acc[BB];
#pragma unroll
    for (int b = 0; b < BB; b++) acc[b] = 0.f;
#pragma unroll 16
    for (int dd = 0; dd < dchunk; dd++) {
        float w = W[(size_t)(d0 + dd) * O + col];
#pragma unroll
        for (int b = 0; b < BB; b++) acc[b] = fmaf(sx[b * dchunk + dd], w, acc[b]);
    }
#pragma unroll
    for (int b = 0; b < BB; b++) atomicAdd(&Y[b * O + col], acc[b]);
}

// ------------------- main streaming kernel: cache copy + raw scores ----------------------
// Pure copies as flat coalesced loops (high MLP); only k_up/kr go through score loop.
__global__ void __launch_bounds__(256)
stream_score(const float* __restrict__ ckv_cache, const float* __restrict__ kr_cache,
             const float* __restrict__ up_cache,
             float* __restrict__ out_ckv, float* __restrict__ out_kr, float* __restrict__ out_up) {
    __shared__ float4 sqc[DD / 4];                   // 4 KB
    __shared__ float4 sqr[DD / 4];                   // 4 KB
    int b    = blockIdx.x / CPB;
    int c    = blockIdx.x % CPB;
    int warp = threadIdx.x >> 5;
    int lane = threadIdx.x & 31;
    int s0   = c * CHUNK;
    int rows = SPAST - s0; if (rows > CHUNK) rows = CHUNK;

    // --- q into shared ---
    sqc[threadIdx.x] = ((const float4*)(g_Qc + b * DD))[threadIdx.x];
    sqr[threadIdx.x] = ((const float4*)(g_Qr + b * DD))[threadIdx.x];

    // --- ckv copy: flat, fully coalesced, independent iterations ---
    {
        const float4* src = (const float4*)(ckv_cache + (size_t)b * SPAST * LOWD) + (size_t)s0 * 128;
        float4*       dst = (float4*)(out_ckv + (size_t)b * STOT * LOWD) + (size_t)s0 * 128;
        int total = rows * 128;
#pragma unroll 4
        for (int i = threadIdx.x; i < total; i += 256)
            __stcs(dst + i, __ldcs(src + i));
    }

    // --- v-half copy: one row-half (256 float4) per iteration, tid = col ---
    {
        const float4* src = (const float4*)(up_cache + ((size_t)b * SPAST + s0) * 2 * DD) + 256 + threadIdx.x;
        float4*       dst = (float4*)(out_up + ((size_t)b * STOT + s0) * 2 * DD) + 256 + threadIdx.x;
#pragma unroll 4
        for (int r = 0; r < rows; r++)
            __stcs(dst + (size_t)r * 512, __ldcs(src + (size_t)r * 512));
    }
    __syncthreads();

    // --- per-warp rows: k_up + kr copy + dot (4-deep explicit load batching) ---
    for (int i = warp; i < rows; i += NWARP) {
        int s = s0 + i;
        const float4* u4 = (const float4*)(up_cache + ((size_t)b * SPAST + s) * 2 * DD);
        const float4* k4 = (const float4*)(kr_cache + ((size_t)b * SPAST + s) * DD);
        float4* ou4 = (float4*)(out_up + ((size_t)b * STOT + s) * 2 * DD);
        float4* ok4 = (float4*)(out_kr + ((size_t)b * STOT + s) * DD);

        float part = 0.f;
#pragma unroll
        for (int h = 0; h < 2; h++) {                // k_up half: 2 batches of 4
            float4 t[4];
#pragma unroll
            for (int j = 0; j < 4; j++) t[j] = __ldcs(u4 + lane + 32 * (4 * h + j));
#pragma unroll
            for (int j = 0; j < 4; j++) {
                __stcs(ou4 + lane + 32 * (4 * h + j), t[j]);
                float4 q = sqc[lane + 32 * (4 * h + j)];
                part += t[j].x * q.x + t[j].y * q.y + t[j].z * q.z + t[j].w * q.w;
            }
        }
#pragma unroll
        for (int h = 0; h < 2; h++) {                // kr: 2 batches of 4
            float4 t[4];
#pragma unroll
            for (int j = 0; j < 4; j++) t[j] = __ldcs(k4 + lane + 32 * (4 * h + j));
#pragma unroll
            for (int j = 0; j < 4; j++) {
                __stcs(ok4 + lane + 32 * (4 * h + j), t[j]);
                float4 q = sqr[lane + 32 * (4 * h + j)];
                part += t[j].x * q.x + t[j].y * q.y + t[j].z * q.z + t[j].w * q.w;
            }
        }
#pragma unroll
        for (int off = 16; off; off >>= 1) part += __shfl_xor_sync(0xffffffffu, part, off);
        if (lane == 0) g_score[b * STOT + s] = part * SCALE;
    }
}

// ------------------- current token: copy new rows + raw score -------------------
__global__ void finalize_cur(float* __restrict__ out_ckv, float* __restrict__ out_kr,
                             float* __restrict__ out_up) {
    int b = blockIdx.x, tid = threadIdx.x;
    {
        const float4* cc = (const float4*)(g_cur_ckv + b * LOWD);
        float4* oc = (float4*)(out_ckv + ((size_t)b * STOT + SPAST) * LOWD);
        for (int i = tid; i < LOWD / 4; i += 256) oc[i] = cc[i];
        const float4* ck = (const float4*)(g_cur_kr + b * DD);
        float4* ok = (float4*)(out_kr + ((size_t)b * STOT + SPAST) * DD);
        for (int i = tid; i < DD / 4; i += 256) ok[i] = ck[i];
        const float4* cu = (const float4*)(g_cur_up + b * 2 * DD);
        float4* ou = (float4*)(out_up + ((size_t)b * STOT + SPAST) * 2 * DD);
        for (int i = tid; i < 2 * DD / 4; i += 256) ou[i] = cu[i];
    }
    float part = 0.f;
    for (int i = tid; i < DD; i += 256) part += g_Qc[b * DD + i] * g_cur_up[b * 2 * DD + i];
    for (int i = tid; i < DD; i += 256) part += g_Qr[b * DD + i] * g_cur_kr[b * DD + i];
    __shared__ float red[256];
    red[tid] = part; __syncthreads();
    for (int s = 128; s; s >>= 1) { if (tid < s) red[tid] += red[tid + s]; __syncthreads(); }
    if (tid == 0) g_score[b * STOT + SPAST] = red[0] * SCALE;
}

// ------------------- exact softmax over 8192 scores -> normalized weights ---------------
__global__ void softmax_k() {
    int b = blockIdx.x, tid = threadIdx.x;
    __shared__ float sred[256];
    __shared__ float sM, sL;
    float M = -1e30f;
    for (int i = tid; i < STOT; i += 256) M = fmaxf(M, g_score[b * STOT + i]);
    sred[tid] = M; __syncthreads();
    for (int s = 128; s; s >>= 1) { if (tid < s) sred[tid] = fmaxf(sred[tid], sred[tid + s]); __syncthreads(); }
    if (tid == 0) sM = sred[0];
    __syncthreads();
    M = sM;
    float L = 0.f;
    for (int i = tid; i < STOT; i += 256) {
        float e = __expf(g_score[b * STOT + i] - M);
        g_w[b * STOT + i] = e;
        L += e;
    }
    sred[tid] = L; __syncthreads();
    for (int s = 128; s; s >>= 1) { if (tid < s) sred[tid] += sred[tid + s]; __syncthreads(); }
    if (tid == 0) sL = sred[0];
    __syncthreads();
    float inv = 1.f / sL;
    for (int i = tid; i < STOT; i += 256) g_w[b * STOT + i] *= inv;
}

// ------------------- attn = w @ v (v = second half of out_up rows) ----------------------
// grid (BB, STOT/VCHUNK) = (8, 64). Each block: 128 rows x full 1024-d, atomic accum.
__global__ void __launch_bounds__(256)
wv_k(const float* __restrict__ out_up) {
    __shared__ float sw[VCHUNK];
    int b = blockIdx.x, tid = threadIdx.x;
    int s0 = blockIdx.y * VCHUNK;
    if (tid < VCHUNK) sw[tid] = g_w[b * STOT + s0 + tid];
    __syncthreads();
    // thread tid covers d = [4*tid, 4*tid+3]
    const float4* base = (const float4*)out_up + ((size_t)(b * STOT + s0)) * (2 * DD / 4)
                         + (DD / 4) + tid;
    float4 a0 = make_float4(0.f,0.f,0.f,0.f), a1 = a0, a2 = a0, a3 = a0;
#pragma unroll 4
    for (int r = 0; r < VCHUNK; r += 4) {
        float4 v0 = __ldcs(base + (size_t)(r + 0) * (2 * DD / 4));
        float4 v1 = __ldcs(base + (size_t)(r + 1) * (2 * DD / 4));
        float4 v2 = __ldcs(base + (size_t)(r + 2) * (2 * DD / 4));
        float4 v3 = __ldcs(base + (size_t)(r + 3) * (2 * DD / 4));
        float w0 = sw[r], w1 = sw[r+1], w2 = sw[r+2], w3 = sw[r+3];
        a0.x = fmaf(w0, v0.x, a0.x); a0.y = fmaf(w0, v0.y, a0.y);
        a0.z = fmaf(w0, v0.z, a0.z); a0.w = fmaf(w0, v0.w, a0.w);
        a1.x = fmaf(w1, v1.x, a1.x); a1.y = fmaf(w1, v1.y, a1.y);
        a1.z = fmaf(w1, v1.z, a1.z); a1.w = fmaf(w1, v1.w, a1.w);
        a2.x = fmaf(w2, v2.x, a2.x); a2.y = fmaf(w2, v2.y, a2.y);
        a2.z = fmaf(w2, v2.z, a2.z); a2.w = fmaf(w2, v2.w, a2.w);
        a3.x = fmaf(w3, v3.x, a3.x); a3.y = fmaf(w3, v3.y, a3.y);
        a3.z = fmaf(w3, v3.z, a3.z); a3.w = fmaf(w3, v3.w, a3.w);
    }
    float4 a;
    a.x = (a0.x + a1.x) + (a2.x + a3.x);
    a.y = (a0.y + a1.y) + (a2.y + a3.y);
    a.z = (a0.z + a1.z) + (a2.z + a3.z);
    a.w = (a0.w + a1.w) + (a2.w + a3.w);
    float* dst = g_attn + b * DD + 4 * tid;
    atomicAdd(dst + 0, a.x);
    atomicAdd(dst + 1, a.y);
    atomicAdd(dst + 2, a.z);
    atomicAdd(dst + 3, a.w);
}

// ------------------- out = attn @ Wo -------------------
// grid (4, 32): 1024 outputs tiled by 256; Din split 32.
__global__ void gemv_wo(const float* __restrict__ Wo, float* __restrict__ Y) {
    __shared__ float sx[BB * 32];
    int o = blockIdx.x * 256 + threadIdx.x;
    int d0 = blockIdx.y * 32;
    if (threadIdx.x < BB * 32) {
        int b = threadIdx.x >> 5, dd = threadIdx.x & 31;
        sx[threadIdx.x] = g_attn[b * DD + d0 + dd];
    }
    __syncthreads();
    float acc[BB];
#pragma unroll
    for (int b = 0; b < BB; b++) acc[b] = 0.f;
#pragma unroll
    for (int dd = 0; dd < 32; dd++) {
        float w = Wo[(size_t)(d0 + dd) * DD + o];
#pragma unroll
        for (int b = 0; b < BB; b++) acc[b] = fmaf(sx[(b << 5) + dd], w, acc[b]);
    }
#pragma unroll
    for (int b = 0; b < BB; b++) atomicAdd(&Y[b * DD + o], acc[b]);
}

// ------------------- launch -------------------
extern "C" void kernel_launch(void* const* d_in, const int* in_sizes, int n_in,
                              void* d_out, int out_size) {
    (void)in_sizes; (void)n_in; (void)out_size;
    const float* x        = (const float*)d_in[0];
    const float* ckv_c    = (const float*)d_in[1];
    const float* kr_c     = (const float*)d_in[2];
    const float* up_c     = (const float*)d_in[3];
    const float* Wdq      = (const float*)d_in[4];
    const float* Wuq      = (const float*)d_in[5];
    const float* Wqr      = (const float*)d_in[6];
    const float* Wdkv     = (const float*)d_in[7];
    const float* Wkr      = (const float*)d_in[8];
    const float* fup      = (const float*)d_in[9];
    const float* Wo       = (const float*)d_in[10];

    float* dout    = (float*)d_out;
    float* out_att = dout;                                     // [8,1,1024]
    float* out_ckv = dout + (size_t)BB * DD;                   // [8,8192,512]
    float* out_kr  = out_ckv + (size_t)BB * STOT * LOWD;       // [8,8192,1024]
    float* out_up  = out_kr  + (size_t)BB * STOT * DD;         // [8,8192,2048]

    zero_scratch<<<64, 256>>>(dout);

    // projection chain (2 fused launches, deep d-split for occupancy)
    proj1<<<dim3(10, 32), 256>>>(x, Wdkv, Wkr, Wdq);
    proj2<<<dim3(16, 32), 256>>>(Wuq, Wqr, fup);

    // big streaming pass: copies + raw scores (no softmax, no accumulators)
    stream_score<<<BB * CPB, 256>>>(ckv_c, kr_c, up_c, out_ckv, out_kr, out_up);

    // current-token rows + its raw score
    finalize_cur<<<BB, 256>>>(out_ckv, out_kr, out_up);

    // exact softmax -> normalized weights
    softmax_k<<<BB, 256>>>();

    // attn = w @ v (reads v back from out_up)
    wv_k<<<dim3(BB, STOT / VCHUNK), 256>>>(out_up);

    // out = attn @ Wo
    gemv_wo<<<dim3(4, 32), 256>>>(Wo, out_att);
}

// round 11
// speedup vs baseline: 2.0224x; 1.1698x over previous
#include <cuda_runtime.h>
#include <math.h>

#define BB 8
#define DD 1024
#define LOWD 512
#define SPAST 8191
#define STOT 8192
#define CPB 256           // chunks (blocks) per batch
#define CHUNK 32          // rows per block
#define NWARP 8
#define SCALE 0.02209708691207961f  // 1/sqrt(2*1024)
#define VCHUNK 128        // rows per v_copy_wv block

// ------------------- device scratch (no allocations allowed) -------------------
__device__ float g_cur_ckv[BB*LOWD];
__device__ float g_cur_kr [BB*DD];
__device__ float g_cur_up [BB*2*DD];
__device__ float g_Cq  [BB*DD];
__device__ float g_Qc  [BB*DD];
__device__ float g_Qr  [BB*DD];
__device__ float g_score[BB*STOT];
__device__ float g_w    [BB*STOT];
__device__ float g_attn [BB*DD];

// ------------------- zero scratch + out_att region -------------------
__global__ void zero_scratch(float* __restrict__ dout) {
    int i = blockIdx.x * 256 + threadIdx.x;           // grid: 64*256 = 16384
    if (i < BB*LOWD)  g_cur_ckv[i] = 0.f;
    if (i < BB*DD) { g_cur_kr[i] = 0.f; g_Cq[i] = 0.f; g_Qc[i] = 0.f;
                     g_Qr[i] = 0.f; g_attn[i] = 0.f; }
    if (i < BB*2*DD)  g_cur_up[i] = 0.f;
    if (i < BB*DD)    dout[i] = 0.f;
}

// ------------------- stage 1: [cur_ckv | cur_kr | Cq] = x @ [Wdkv | Wkr | Wdq] --------
// grid (10, 32): 2560 outputs tiled by 256; Din=1024 split 32 (32 each); atomic accum.
__global__ void proj1(const float* __restrict__ x,
                      const float* __restrict__ Wdkv, const float* __restrict__ Wkr,
                      const float* __restrict__ Wdq) {
    __shared__ float sx[BB * 32];
    int og = blockIdx.x * 256 + threadIdx.x;         // 0..2559
    int d0 = blockIdx.y * 32;
    if (threadIdx.x < BB * 32) {
        int b = threadIdx.x >> 5, dd = threadIdx.x & 31;
        sx[threadIdx.x] = x[b * DD + d0 + dd];
    }
    __syncthreads();
    const float* W; float* Y; int O; int col;
    if (og < 512)       { W = Wdkv; Y = g_cur_ckv; O = LOWD; col = og; }
    else if (og < 1536) { W = Wkr;  Y = g_cur_kr;  O = DD;   col = og - 512; }
    else                { W = Wdq;  Y = g_Cq;      O = DD;   col = og - 1536; }
    float acc[BB];
#pragma unroll
    for (int b = 0; b < BB; b++) acc[b] = 0.f;
#pragma unroll
    for (int dd = 0; dd < 32; dd++) {
        float w = W[(size_t)(d0 + dd) * O + col];
#pragma unroll
        for (int b = 0; b < BB; b++) acc[b] = fmaf(sx[(b << 5) + dd], w, acc[b]);
    }
#pragma unroll
    for (int b = 0; b < BB; b++) atomicAdd(&Y[b * O + col], acc[b]);
}

// ------------------- stage 2: [Qc | Qr] = Cq @ [Wuq|Wqr]; cur_up = cur_ckv @ fup -------
// grid (16, 32): 4096 outputs tiled by 256. Ranges align to block boundaries.
__global__ void proj2(const float* __restrict__ Wuq, const float* __restrict__ Wqr,
                      const float* __restrict__ fup) {
    __shared__ float sx[BB * 32];
    int og = blockIdx.x * 256 + threadIdx.x;         // 0..4095
    const float* W; const float* X; float* Y; int O, col, Din;
    if (og < 1024)      { W = Wuq; X = g_Cq;      Y = g_Qc;     O = DD;     col = og;        Din = DD;   }
    else if (og < 2048) { W = Wqr; X = g_Cq;      Y = g_Qr;     O = DD;     col = og - 1024; Din = DD;   }
    else                { W = fup; X = g_cur_ckv; Y = g_cur_up; O = 2 * DD; col = og - 2048; Din = LOWD; }
    int dchunk = Din >> 5;                            // 32 or 16
    int d0 = blockIdx.y * dchunk;
    if (threadIdx.x < BB * dchunk) {
        int b = threadIdx.x / dchunk, dd = threadIdx.x - b * dchunk;
        sx[b * dchunk + dd] = X[b * Din + d0 + dd];
    }
    __syncthreads();
    float acc[BB];
#pragma unroll
    for (int b = 0; b < BB; b++) acc[b] = 0.f;
#pragma unroll 16
    for (int dd = 0; dd < dchunk; dd++) {
        float w = W[(size_t)(d0 + dd) * O + col];
#pragma unroll
        for (int b = 0; b < BB; b++) acc[b] = fmaf(sx[b * dchunk + dd], w, acc[b]);
    }
#pragma unroll
    for (int b = 0; b < BB; b++) atomicAdd(&Y[b * O + col], acc[b]);
}

// ------------------- streaming kernel: ckv/kr/k_up copy + raw scores (NO v) -------------
__global__ void __launch_bounds__(256)
stream_score(const float* __restrict__ ckv_cache, const float* __restrict__ kr_cache,
             const float* __restrict__ up_cache,
             float* __restrict__ out_ckv, float* __restrict__ out_kr, float* __restrict__ out_up) {
    __shared__ float4 sqc[DD / 4];                   // 4 KB
    __shared__ float4 sqr[DD / 4];                   // 4 KB
    int b    = blockIdx.x / CPB;
    int c    = blockIdx.x % CPB;
    int warp = threadIdx.x >> 5;
    int lane = threadIdx.x & 31;
    int s0   = c * CHUNK;
    int rows = SPAST - s0; if (rows > CHUNK) rows = CHUNK;

    // --- q into shared ---
    sqc[threadIdx.x] = ((const float4*)(g_Qc + b * DD))[threadIdx.x];
    sqr[threadIdx.x] = ((const float4*)(g_Qr + b * DD))[threadIdx.x];

    // --- ckv copy: flat, fully coalesced, independent iterations ---
    {
        const float4* src = (const float4*)(ckv_cache + (size_t)b * SPAST * LOWD) + (size_t)s0 * 128;
        float4*       dst = (float4*)(out_ckv + (size_t)b * STOT * LOWD) + (size_t)s0 * 128;
        int total = rows * 128;
#pragma unroll 4
        for (int i = threadIdx.x; i < total; i += 256)
            __stcs(dst + i, __ldcs(src + i));
    }
    __syncthreads();

    // --- per-warp rows: k_up + kr copy + dot (4-deep explicit load batching) ---
    for (int i = warp; i < rows; i += NWARP) {
        int s = s0 + i;
        const float4* u4 = (const float4*)(up_cache + ((size_t)b * SPAST + s) * 2 * DD);
        const float4* k4 = (const float4*)(kr_cache + ((size_t)b * SPAST + s) * DD);
        float4* ou4 = (float4*)(out_up + ((size_t)b * STOT + s) * 2 * DD);
        float4* ok4 = (float4*)(out_kr + ((size_t)b * STOT + s) * DD);

        float part = 0.f;
#pragma unroll
        for (int h = 0; h < 2; h++) {                // k_up half: 2 batches of 4
            float4 t[4];
#pragma unroll
            for (int j = 0; j < 4; j++) t[j] = __ldcs(u4 + lane + 32 * (4 * h + j));
#pragma unroll
            for (int j = 0; j < 4; j++) {
                __stcs(ou4 + lane + 32 * (4 * h + j), t[j]);
                float4 q = sqc[lane + 32 * (4 * h + j)];
                part += t[j].x * q.x + t[j].y * q.y + t[j].z * q.z + t[j].w * q.w;
            }
        }
#pragma unroll
        for (int h = 0; h < 2; h++) {                // kr: 2 batches of 4
            float4 t[4];
#pragma unroll
            for (int j = 0; j < 4; j++) t[j] = __ldcs(k4 + lane + 32 * (4 * h + j));
#pragma unroll
            for (int j = 0; j < 4; j++) {
                __stcs(ok4 + lane + 32 * (4 * h + j), t[j]);
                float4 q = sqr[lane + 32 * (4 * h + j)];
                part += t[j].x * q.x + t[j].y * q.y + t[j].z * q.z + t[j].w * q.w;
            }
        }
#pragma unroll
        for (int off = 16; off; off >>= 1) part += __shfl_xor_sync(0xffffffffu, part, off);
        if (lane == 0) g_score[b * STOT + s] = part * SCALE;
    }
}

// ------------------- current token: copy new rows + raw score -------------------
__global__ void finalize_cur(float* __restrict__ out_ckv, float* __restrict__ out_kr,
                             float* __restrict__ out_up) {
    int b = blockIdx.x, tid = threadIdx.x;
    {
        const float4* cc = (const float4*)(g_cur_ckv + b * LOWD);
        float4* oc = (float4*)(out_ckv + ((size_t)b * STOT + SPAST) * LOWD);
        for (int i = tid; i < LOWD / 4; i += 256) oc[i] = cc[i];
        const float4* ck = (const float4*)(g_cur_kr + b * DD);
        float4* ok = (float4*)(out_kr + ((size_t)b * STOT + SPAST) * DD);
        for (int i = tid; i < DD / 4; i += 256) ok[i] = ck[i];
        const float4* cu = (const float4*)(g_cur_up + b * 2 * DD);
        float4* ou = (float4*)(out_up + ((size_t)b * STOT + SPAST) * 2 * DD);
        for (int i = tid; i < 2 * DD / 4; i += 256) ou[i] = cu[i];
    }
    float part = 0.f;
    for (int i = tid; i < DD; i += 256) part += g_Qc[b * DD + i] * g_cur_up[b * 2 * DD + i];
    for (int i = tid; i < DD; i += 256) part += g_Qr[b * DD + i] * g_cur_kr[b * DD + i];
    __shared__ float red[256];
    red[tid] = part; __syncthreads();
    for (int s = 128; s; s >>= 1) { if (tid < s) red[tid] += red[tid + s]; __syncthreads(); }
    if (tid == 0) g_score[b * STOT + SPAST] = red[0] * SCALE;
}

// ------------------- exact softmax over 8192 scores -> normalized weights ---------------
__global__ void softmax_k() {
    int b = blockIdx.x, tid = threadIdx.x;
    __shared__ float sred[256];
    __shared__ float sM, sL;
    float M = -1e30f;
    for (int i = tid; i < STOT; i += 256) M = fmaxf(M, g_score[b * STOT + i]);
    sred[tid] = M; __syncthreads();
    for (int s = 128; s; s >>= 1) { if (tid < s) sred[tid] = fmaxf(sred[tid], sred[tid + s]); __syncthreads(); }
    if (tid == 0) sM = sred[0];
    __syncthreads();
    M = sM;
    float L = 0.f;
    for (int i = tid; i < STOT; i += 256) {
        float e = __expf(g_score[b * STOT + i] - M);
        g_w[b * STOT + i] = e;
        L += e;
    }
    sred[tid] = L; __syncthreads();
    for (int s = 128; s; s >>= 1) { if (tid < s) sred[tid] += sred[tid + s]; __syncthreads(); }
    if (tid == 0) sL = sred[0];
    __syncthreads();
    float inv = 1.f / sL;
    for (int i = tid; i < STOT; i += 256) g_w[b * STOT + i] *= inv;
}

// ------------------- v copy + attn accumulation fused (post-softmax) --------------------
// grid (BB, STOT/VCHUNK) = (8, 64). Each block: VCHUNK rows; thread tid = d cols [4t,4t+3].
// Reads v once from up_cache, writes the out_up v-half copy AND accumulates w·v.
__global__ void __launch_bounds__(256)
v_copy_wv(const float* __restrict__ up_cache, float* __restrict__ out_up) {
    __shared__ float sw[VCHUNK];
    int b = blockIdx.x, tid = threadIdx.x;
    int s0 = blockIdx.y * VCHUNK;
    if (tid < VCHUNK) sw[tid] = g_w[b * STOT + s0 + tid];
    __syncthreads();
    int rows = SPAST - s0; if (rows > VCHUNK) rows = VCHUNK;   // last block: 127 cache rows
    const float4* src = (const float4*)(up_cache + ((size_t)b * SPAST + s0) * 2 * DD) + 256 + tid;
    float4*       dst = (float4*)(out_up + ((size_t)b * STOT + s0) * 2 * DD) + 256 + tid;

    float4 a0 = make_float4(0.f,0.f,0.f,0.f), a1 = a0, a2 = a0, a3 = a0;
    int r = 0;
    for (; r + 4 <= rows; r += 4) {
        float4 v0 = __ldcs(src + (size_t)(r + 0) * 512);
        float4 v1 = __ldcs(src + (size_t)(r + 1) * 512);
        float4 v2 = __ldcs(src + (size_t)(r + 2) * 512);
        float4 v3 = __ldcs(src + (size_t)(r + 3) * 512);
        __stcs(dst + (size_t)(r + 0) * 512, v0);
        __stcs(dst + (size_t)(r + 1) * 512, v1);
        __stcs(dst + (size_t)(r + 2) * 512, v2);
        __stcs(dst + (size_t)(r + 3) * 512, v3);
        float w0 = sw[r], w1 = sw[r+1], w2 = sw[r+2], w3 = sw[r+3];
        a0.x = fmaf(w0, v0.x, a0.x); a0.y = fmaf(w0, v0.y, a0.y);
        a0.z = fmaf(w0, v0.z, a0.z); a0.w = fmaf(w0, v0.w, a0.w);
        a1.x = fmaf(w1, v1.x, a1.x); a1.y = fmaf(w1, v1.y, a1.y);
        a1.z = fmaf(w1, v1.z, a1.z); a1.w = fmaf(w1, v1.w, a1.w);
        a2.x = fmaf(w2, v2.x, a2.x); a2.y = fmaf(w2, v2.y, a2.y);
        a2.z = fmaf(w2, v2.z, a2.z); a2.w = fmaf(w2, v2.w, a2.w);
        a3.x = fmaf(w3, v3.x, a3.x); a3.y = fmaf(w3, v3.y, a3.y);
        a3.z = fmaf(w3, v3.z, a3.z); a3.w = fmaf(w3, v3.w, a3.w);
    }
    for (; r < rows; r++) {
        float4 v = __ldcs(src + (size_t)r * 512);
        __stcs(dst + (size_t)r * 512, v);
        float w = sw[r];
        a0.x = fmaf(w, v.x, a0.x); a0.y = fmaf(w, v.y, a0.y);
        a0.z = fmaf(w, v.z, a0.z); a0.w = fmaf(w, v.w, a0.w);
    }
    // current-token row (v already copied to out_up by finalize_cur; read from scratch)
    if (s0 + VCHUNK > SPAST) {
        float w = sw[SPAST - s0];
        float4 v = ((const float4*)(g_cur_up + b * 2 * DD + DD))[tid];
        a0.x = fmaf(w, v.x, a0.x); a0.y = fmaf(w, v.y, a0.y);
        a0.z = fmaf(w, v.z, a0.z); a0.w = fmaf(w, v.w, a0.w);
    }
    float4 a;
    a.x = (a0.x + a1.x) + (a2.x + a3.x);
    a.y = (a0.y + a1.y) + (a2.y + a3.y);
    a.z = (a0.z + a1.z) + (a2.z + a3.z);
    a.w = (a0.w + a1.w) + (a2.w + a3.w);
    float* dstA = g_attn + b * DD + 4 * tid;
    atomicAdd(dstA + 0, a.x);
    atomicAdd(dstA + 1, a.y);
    atomicAdd(dstA + 2, a.z);
    atomicAdd(dstA + 3, a.w);
}

// ------------------- out = attn @ Wo -------------------
// grid (4, 32): 1024 outputs tiled by 256; Din split 32.
__global__ void gemv_wo(const float* __restrict__ Wo, float* __restrict__ Y) {
    __shared__ float sx[BB * 32];
    int o = blockIdx.x * 256 + threadIdx.x;
    int d0 = blockIdx.y * 32;
    if (threadIdx.x < BB * 32) {
        int b = threadIdx.x >> 5, dd = threadIdx.x & 31;
        sx[threadIdx.x] = g_attn[b * DD + d0 + dd];
    }
    __syncthreads();
    float acc[BB];
#pragma unroll
    for (int b = 0; b < BB; b++) acc[b] = 0.f;
#pragma unroll
    for (int dd = 0; dd < 32; dd++) {
        float w = Wo[(size_t)(d0 + dd) * DD + o];
#pragma unroll
        for (int b = 0; b < BB; b++) acc[b] = fmaf(sx[(b << 5) + dd], w, acc[b]);
    }
#pragma unroll
    for (int b = 0; b < BB; b++) atomicAdd(&Y[b * DD + o], acc[b]);
}

// ------------------- launch -------------------
extern "C" void kernel_launch(void* const* d_in, const int* in_sizes, int n_in,
                              void* d_out, int out_size) {
    (void)in_sizes; (void)n_in; (void)out_size;
    const float* x        = (const float*)d_in[0];
    const float* ckv_c    = (const float*)d_in[1];
    const float* kr_c     = (const float*)d_in[2];
    const float* up_c     = (const float*)d_in[3];
    const float* Wdq      = (const float*)d_in[4];
    const float* Wuq      = (const float*)d_in[5];
    const float* Wqr      = (const float*)d_in[6];
    const float* Wdkv     = (const float*)d_in[7];
    const float* Wkr      = (const float*)d_in[8];
    const float* fup      = (const float*)d_in[9];
    const float* Wo       = (const float*)d_in[10];

    float* dout    = (float*)d_out;
    float* out_att = dout;                                     // [8,1,1024]
    float* out_ckv = dout + (size_t)BB * DD;                   // [8,8192,512]
    float* out_kr  = out_ckv + (size_t)BB * STOT * LOWD;       // [8,8192,1024]
    float* out_up  = out_kr  + (size_t)BB * STOT * DD;         // [8,8192,2048]

    zero_scratch<<<64, 256>>>(dout);

    // projection chain (2 fused launches, deep d-split for occupancy)
    proj1<<<dim3(10, 32), 256>>>(x, Wdkv, Wkr, Wdq);
    proj2<<<dim3(16, 32), 256>>>(Wuq, Wqr, fup);

    // streaming pass: ckv/kr/k_up copies + raw scores (v deferred)
    stream_score<<<BB * CPB, 256>>>(ckv_c, kr_c, up_c, out_ckv, out_kr, out_up);

    // current-token rows + its raw score
    finalize_cur<<<BB, 256>>>(out_ckv, out_kr, out_up);

    // exact softmax -> normalized weights
    softmax_k<<<BB, 256>>>();

    // v copy + attn accumulation in one pass (reads v exactly once)
    v_copy_wv<<<dim3(BB, STOT / VCHUNK), 256>>>(up_c, out_up);

    // out = attn @ Wo
    gemv_wo<<<dim3(4, 32), 256>>>(Wo, out_att);
}

// round 13
// speedup vs baseline: 2.0388x; 1.0081x over previous
#include <cuda_runtime.h>
#include <math.h>

#define BB 8
#define DD 1024
#define LOWD 512
#define SPAST 8191
#define STOT 8192
#define CPB 256           // chunks (blocks) per batch
#define CHUNK 32          // rows per block
#define NWARP 8
#define SCALE 0.02209708691207961f  // 1/sqrt(2*1024)
#define VCHUNK 64         // rows per v_copy_wv block

// ------------------- device scratch (no allocations allowed) -------------------
__device__ float g_cur_ckv[BB*LOWD];
__device__ float g_cur_kr [BB*DD];
__device__ float g_cur_up [BB*2*DD];
__device__ float g_Cq  [BB*DD];
__device__ float g_Qc  [BB*DD];
__device__ float g_Qr  [BB*DD];
__device__ float g_score[BB*STOT];
__device__ float g_w    [BB*STOT];
__device__ float g_attn [BB*DD];

// ------------------- zero scratch + out_att region -------------------
__global__ void zero_scratch(float* __restrict__ dout) {
    int i = blockIdx.x * 256 + threadIdx.x;           // grid: 64*256 = 16384
    if (i < BB*LOWD)  g_cur_ckv[i] = 0.f;
    if (i < BB*DD) { g_cur_kr[i] = 0.f; g_Cq[i] = 0.f; g_Qc[i] = 0.f;
                     g_Qr[i] = 0.f; g_attn[i] = 0.f; }
    if (i < BB*2*DD)  g_cur_up[i] = 0.f;
    if (i < BB*DD)    dout[i] = 0.f;
}

// ------------------- stage 1: [cur_ckv | cur_kr | Cq] = x @ [Wdkv | Wkr | Wdq] --------
// grid (10, 32): 2560 outputs tiled by 256; Din=1024 split 32 (32 each); atomic accum.
__global__ void proj1(const float* __restrict__ x,
                      const float* __restrict__ Wdkv, const float* __restrict__ Wkr,
                      const float* __restrict__ Wdq) {
    __shared__ float sx[BB * 32];
    int og = blockIdx.x * 256 + threadIdx.x;         // 0..2559
    int d0 = blockIdx.y * 32;
    if (threadIdx.x < BB * 32) {
        int b = threadIdx.x >> 5, dd = threadIdx.x & 31;
        sx[threadIdx.x] = x[b * DD + d0 + dd];
    }
    __syncthreads();
    const float* W; float* Y; int O; int col;
    if (og < 512)       { W = Wdkv; Y = g_cur_ckv; O = LOWD; col = og; }
    else if (og < 1536) { W = Wkr;  Y = g_cur_kr;  O = DD;   col = og - 512; }
    else                { W = Wdq;  Y = g_Cq;      O = DD;   col = og - 1536; }
    float acc[BB];
#pragma unroll
    for (int b = 0; b < BB; b++) acc[b] = 0.f;
#pragma unroll
    for (int dd = 0; dd < 32; dd++) {
        float w = W[(size_t)(d0 + dd) * O + col];
#pragma unroll
        for (int b = 0; b < BB; b++) acc[b] = fmaf(sx[(b << 5) + dd], w, acc[b]);
    }
#pragma unroll
    for (int b = 0; b < BB; b++) atomicAdd(&Y[b * O + col], acc[b]);
}

// ------------------- stage 2: [Qc | Qr] = Cq @ [Wuq|Wqr]; cur_up = cur_ckv @ fup -------
// grid (16, 32): 4096 outputs tiled by 256. Ranges align to block boundaries.
__global__ void proj2(const float* __restrict__ Wuq, const float* __restrict__ Wqr,
                      const float* __restrict__ fup) {
    __shared__ float sx[BB * 32];
    int og = blockIdx.x * 256 + threadIdx.x;         // 0..4095
    const float* W; const float* X; float* Y; int O, col, Din;
    if (og < 1024)      { W = Wuq; X = g_Cq;      Y = g_Qc;     O = DD;     col = og;        Din = DD;   }
    else if (og < 2048) { W = Wqr; X = g_Cq;      Y = g_Qr;     O = DD;     col = og - 1024; Din = DD;   }
    else                { W = fup; X = g_cur_ckv; Y = g_cur_up; O = 2 * DD; col = og - 2048; Din = LOWD; }
    int dchunk = Din >> 5;                            // 32 or 16
    int d0 = blockIdx.y * dchunk;
    if (threadIdx.x < BB * dchunk) {
        int b = threadIdx.x / dchunk, dd = threadIdx.x - b * dchunk;
        sx[b * dchunk + dd] = X[b * Din + d0 + dd];
    }
    __syncthreads();
    float acc[BB];
#pragma unroll
    for (int b = 0; b < BB; b++) acc[b] = 0.f;
#pragma unroll 16
    for (int dd = 0; dd < dchunk; dd++) {
        float w = W[(size_t)(d0 + dd) * O + col];
#pragma unroll
        for (int b = 0; b < BB; b++) acc[b] = fmaf(sx[b * dchunk + dd], w, acc[b]);
    }
#pragma unroll
    for (int b = 0; b < BB; b++) atomicAdd(&Y[b * O + col], acc[b]);
}

// ------------------- streaming kernel: ckv/kr/k_up copy + raw scores (NO v) -------------
// 8-deep interleaved load batching; 4 CTAs/SM pinned for 256 outstanding loads/SM.
__global__ void __launch_bounds__(256, 4)
stream_score(const float* __restrict__ ckv_cache, const float* __restrict__ kr_cache,
             const float* __restrict__ up_cache,
             float* __restrict__ out_ckv, float* __restrict__ out_kr, float* __restrict__ out_up) {
    __shared__ float4 sqc[DD / 4];                   // 4 KB
    __shared__ float4 sqr[DD / 4];                   // 4 KB
    int b    = blockIdx.x / CPB;
    int c    = blockIdx.x % CPB;
    int warp = threadIdx.x >> 5;
    int lane = threadIdx.x & 31;
    int s0   = c * CHUNK;
    int rows = SPAST - s0; if (rows > CHUNK) rows = CHUNK;

    // --- q into shared ---
    sqc[threadIdx.x] = ((const float4*)(g_Qc + b * DD))[threadIdx.x];
    sqr[threadIdx.x] = ((const float4*)(g_Qr + b * DD))[threadIdx.x];

    // --- ckv copy: flat, fully coalesced, independent iterations ---
    {
        const float4* src = (const float4*)(ckv_cache + (size_t)b * SPAST * LOWD) + (size_t)s0 * 128;
        float4*       dst = (float4*)(out_ckv + (size_t)b * STOT * LOWD) + (size_t)s0 * 128;
        int total = rows * 128;
#pragma unroll 4
        for (int i = threadIdx.x; i < total; i += 256)
            __stcs(dst + i, __ldcs(src + i));
    }
    __syncthreads();

    // --- per-warp rows: k_up + kr copy + dot (8-deep interleaved load batching) ---
    for (int i = warp; i < rows; i += NWARP) {
        int s = s0 + i;
        const float4* u4 = (const float4*)(up_cache + ((size_t)b * SPAST + s) * 2 * DD);
        const float4* k4 = (const float4*)(kr_cache + ((size_t)b * SPAST + s) * DD);
        float4* ou4 = (float4*)(out_up + ((size_t)b * STOT + s) * 2 * DD);
        float4* ok4 = (float4*)(out_kr + ((size_t)b * STOT + s) * DD);

        float part = 0.f;
#pragma unroll
        for (int h = 0; h < 2; h++) {
            float4 tu[4], tk[4];
#pragma unroll
            for (int j = 0; j < 4; j++) tu[j] = __ldcs(u4 + lane + 32 * (4 * h + j));
#pragma unroll
            for (int j = 0; j < 4; j++) tk[j] = __ldcs(k4 + lane + 32 * (4 * h + j));
#pragma unroll
            for (int j = 0; j < 4; j++) {
                __stcs(ou4 + lane + 32 * (4 * h + j), tu[j]);
                float4 q = sqc[lane + 32 * (4 * h + j)];
                part += tu[j].x * q.x + tu[j].y * q.y + tu[j].z * q.z + tu[j].w * q.w;
            }
#pragma unroll
            for (int j = 0; j < 4; j++) {
                __stcs(ok4 + lane + 32 * (4 * h + j), tk[j]);
                float4 q = sqr[lane + 32 * (4 * h + j)];
                part += tk[j].x * q.x + tk[j].y * q.y + tk[j].z * q.z + tk[j].w * q.w;
            }
        }
#pragma unroll
        for (int off = 16; off; off >>= 1) part += __shfl_xor_sync(0xffffffffu, part, off);
        if (lane == 0) g_score[b * STOT + s] = part * SCALE;
    }
}

// ------------------- current token rows + cur score + exact softmax (merged) ------------
__global__ void fin_softmax(float* __restrict__ out_ckv, float* __restrict__ out_kr,
                            float* __restrict__ out_up) {
    int b = blockIdx.x, tid = threadIdx.x;
    // copy new rows into position s = SPAST
    {
        const float4* cc = (const float4*)(g_cur_ckv + b * LOWD);
        float4* oc = (float4*)(out_ckv + ((size_t)b * STOT + SPAST) * LOWD);
        for (int i = tid; i < LOWD / 4; i += 256) oc[i] = cc[i];
        const float4* ck = (const float4*)(g_cur_kr + b * DD);
        float4* ok = (float4*)(out_kr + ((size_t)b * STOT + SPAST) * DD);
        for (int i = tid; i < DD / 4; i += 256) ok[i] = ck[i];
        const float4* cu = (const float4*)(g_cur_up + b * 2 * DD);
        float4* ou = (float4*)(out_up + ((size_t)b * STOT + SPAST) * 2 * DD);
        for (int i = tid; i < 2 * DD / 4; i += 256) ou[i] = cu[i];
    }
    // current-token raw score
    float part = 0.f;
    for (int i = tid; i < DD; i += 256) part += g_Qc[b * DD + i] * g_cur_up[b * 2 * DD + i];
    for (int i = tid; i < DD; i += 256) part += g_Qr[b * DD + i] * g_cur_kr[b * DD + i];
    __shared__ float sred[256];
    __shared__ float sM, sL;
    sred[tid] = part; __syncthreads();
    for (int s = 128; s; s >>= 1) { if (tid < s) sred[tid] += sred[tid + s]; __syncthreads(); }
    if (tid == 0) g_score[b * STOT + SPAST] = sred[0] * SCALE;
    __syncthreads();
    // exact softmax over all 8192 scores
    float M = -1e30f;
    for (int i = tid; i < STOT; i += 256) M = fmaxf(M, g_score[b * STOT + i]);
    sred[tid] = M; __syncthreads();
    for (int s = 128; s; s >>= 1) { if (tid < s) sred[tid] = fmaxf(sred[tid], sred[tid + s]); __syncthreads(); }
    if (tid == 0) sM = sred[0];
    __syncthreads();
    M = sM;
    float L = 0.f;
    for (int i = tid; i < STOT; i += 256) {
        float e = __expf(g_score[b * STOT + i] - M);
        g_w[b * STOT + i] = e;
        L += e;
    }
    sred[tid] = L; __syncthreads();
    for (int s = 128; s; s >>= 1) { if (tid < s) sred[tid] += sred[tid + s]; __syncthreads(); }
    if (tid == 0) sL = sred[0];
    __syncthreads();
    float inv = 1.f / sL;
    for (int i = tid; i < STOT; i += 256) g_w[b * STOT + i] *= inv;
}

// ------------------- v copy + attn accumulation fused (post-softmax) --------------------
// grid (BB, STOT/VCHUNK) = (8, 128). 8-deep load batching; 4 CTAs/SM pinned.
__global__ void __launch_bounds__(256, 4)
v_copy_wv(const float* __restrict__ up_cache, float* __restrict__ out_up) {
    __shared__ float sw[VCHUNK];
    int b = blockIdx.x, tid = threadIdx.x;
    int s0 = blockIdx.y * VCHUNK;
    if (tid < VCHUNK) sw[tid] = g_w[b * STOT + s0 + tid];
    __syncthreads();
    int rows = SPAST - s0; if (rows > VCHUNK) rows = VCHUNK;   // last block: 63 cache rows
    const float4* src = (const float4*)(up_cache + ((size_t)b * SPAST + s0) * 2 * DD) + 256 + tid;
    float4*       dst = (float4*)(out_up + ((size_t)b * STOT + s0) * 2 * DD) + 256 + tid;

    float4 a0 = make_float4(0.f,0.f,0.f,0.f), a1 = a0, a2 = a0, a3 = a0;
    int r = 0;
    for (; r + 8 <= rows; r += 8) {
        float4 v[8];
#pragma unroll
        for (int j = 0; j < 8; j++) v[j] = __ldcs(src + (size_t)(r + j) * 512);
#pragma unroll
        for (int j = 0; j < 8; j++) __stcs(dst + (size_t)(r + j) * 512, v[j]);
#pragma unroll
        for (int j = 0; j < 4; j++) {
            float wa = sw[r + 2 * j], wb = sw[r + 2 * j + 1];
            float4 va = v[2 * j], vb = v[2 * j + 1];
            float4* A = (j == 0) ? &a0 : (j == 1) ? &a1 : (j == 2) ? &a2 : &a3;
            A->x = fmaf(wa, va.x, A->x); A->y = fmaf(wa, va.y, A->y);
            A->z = fmaf(wa, va.z, A->z); A->w = fmaf(wa, va.w, A->w);
            A->x = fmaf(wb, vb.x, A->x); A->y = fmaf(wb, vb.y, A->y);
            A->z = fmaf(wb, vb.z, A->z); A->w = fmaf(wb, vb.w, A->w);
        }
    }
    for (; r < rows; r++) {
        float4 v = __ldcs(src + (size_t)r * 512);
        __stcs(dst + (size_t)r * 512, v);
        float w = sw[r];
        a0.x = fmaf(w, v.x, a0.x); a0.y = fmaf(w, v.y, a0.y);
        a0.z = fmaf(w, v.z, a0.z); a0.w = fmaf(w, v.w, a0.w);
    }
    // current-token row (v already copied to out_up by fin_softmax; read from scratch)
    if (s0 + VCHUNK > SPAST) {
        float w = sw[SPAST - s0];
        float4 v = ((const float4*)(g_cur_up + b * 2 * DD + DD))[tid];
        a0.x = fmaf(w, v.x, a0.x); a0.y = fmaf(w, v.y, a0.y);
        a0.z = fmaf(w, v.z, a0.z); a0.w = fmaf(w, v.w, a0.w);
    }
    float4 a;
    a.x = (a0.x + a1.x) + (a2.x + a3.x);
    a.y = (a0.y + a1.y) + (a2.y + a3.y);
    a.z = (a0.z + a1.z) + (a2.z + a3.z);
    a.w = (a0.w + a1.w) + (a2.w + a3.w);
    float* dstA = g_attn + b * DD + 4 * tid;
    atomicAdd(dstA + 0, a.x);
    atomicAdd(dstA + 1, a.y);
    atomicAdd(dstA + 2, a.z);
    atomicAdd(dstA + 3, a.w);
}

// ------------------- out = attn @ Wo -------------------
// grid (4, 32): 1024 outputs tiled by 256; Din split 32.
__global__ void gemv_wo(const float* __restrict__ Wo, float* __restrict__ Y) {
    __shared__ float sx[BB * 32];
    int o = blockIdx.x * 256 + threadIdx.x;
    int d0 = blockIdx.y * 32;
    if (threadIdx.x < BB * 32) {
        int b = threadIdx.x >> 5, dd = threadIdx.x & 31;
        sx[threadIdx.x] = g_attn[b * DD + d0 + dd];
    }
    __syncthreads();
    float acc[BB];
#pragma unroll
    for (int b = 0; b < BB; b++) acc[b] = 0.f;
#pragma unroll
    for (int dd = 0; dd < 32; dd++) {
        float w = Wo[(size_t)(d0 + dd) * DD + o];
#pragma unroll
        for (int b = 0; b < BB; b++) acc[b] = fmaf(sx[(b << 5) + dd], w, acc[b]);
    }
#pragma unroll
    for (int b = 0; b < BB; b++) atomicAdd(&Y[b * DD + o], acc[b]);
}

// ------------------- launch -------------------
extern "C" void kernel_launch(void* const* d_in, const int* in_sizes, int n_in,
                              void* d_out, int out_size) {
    (void)in_sizes; (void)n_in; (void)out_size;
    const float* x        = (const float*)d_in[0];
    const float* ckv_c    = (const float*)d_in[1];
    const float* kr_c     = (const float*)d_in[2];
    const float* up_c     = (const float*)d_in[3];
    const float* Wdq      = (const float*)d_in[4];
    const float* Wuq      = (const float*)d_in[5];
    const float* Wqr      = (const float*)d_in[6];
    const float* Wdkv     = (const float*)d_in[7];
    const float* Wkr      = (const float*)d_in[8];
    const float* fup      = (const float*)d_in[9];
    const float* Wo       = (const float*)d_in[10];

    float* dout    = (float*)d_out;
    float* out_att = dout;                                     // [8,1,1024]
    float* out_ckv = dout + (size_t)BB * DD;                   // [8,8192,512]
    float* out_kr  = out_ckv + (size_t)BB * STOT * LOWD;       // [8,8192,1024]
    float* out_up  = out_kr  + (size_t)BB * STOT * DD;         // [8,8192,2048]

    zero_scratch<<<64, 256>>>(dout);

    // projection chain (2 fused launches, deep d-split for occupancy)
    proj1<<<dim3(10, 32), 256>>>(x, Wdkv, Wkr, Wdq);
    proj2<<<dim3(16, 32), 256>>>(Wuq, Wqr, fup);

    // streaming pass: ckv/kr/k_up copies + raw scores (v deferred)
    stream_score<<<BB * CPB, 256>>>(ckv_c, kr_c, up_c, out_ckv, out_kr, out_up);

    // current-token rows + cur score + exact softmax (merged)
    fin_softmax<<<BB, 256>>>(out_ckv, out_kr, out_up);

    // v copy + attn accumulation in one pass (reads v exactly once)
    v_copy_wv<<<dim3(BB, STOT / VCHUNK), 256>>>(up_c, out_up);

    // out = attn @ Wo
    gemv_wo<<<dim3(4, 32), 256>>>(Wo, out_att);
}